// round 3
// baseline (speedup 1.0000x reference)
#include <cuda_runtime.h>
#include <math.h>

// Problem constants (fixed shapes)
#define T_STEPS 512
#define BATCH   32
#define DIM     1024
#define BD      (BATCH*DIM)       // 32768
#define NCTA    128               // recurrence persistent CTAs (<= 148 SMs -> all co-resident)
#define NTHR    256
#define EPB     8                 // e-rows of W_h per CTA: 128*8 = 1024
#define WPAD    1028              // smem row stride (floats): bank-conflict-free quads

// Scratch (device globals: allocation-free rule)
__device__ float    g_wx[T_STEPS*BD];       // alpha*(x@W^T + b), 64 MB
__device__ float    g_part[BATCH*NCTA];     // per-CTA partial sumsq per batch
__device__ unsigned g_cnt;                   // barrier arrival counter (returns to 0)
__device__ volatile unsigned g_gen;          // barrier generation (monotone)

// ---------------------------------------------------------------------------
// Software grid barrier (sense-reversing). All NCTA CTAs are co-resident.
// ---------------------------------------------------------------------------
__device__ __forceinline__ void grid_bar() {
    __threadfence();          // publish this thread's prior global writes
    __syncthreads();
    if (threadIdx.x == 0) {
        unsigned gen = g_gen; // must read BEFORE arriving
        if (atomicAdd(&g_cnt, 1u) == (unsigned)(NCTA - 1)) {
            g_cnt = 0u;
            __threadfence();
            g_gen = gen + 1u; // release
        } else {
            while (g_gen == gen) { /* spin on L2 (volatile) */ }
        }
    }
    __syncthreads();
    __threadfence();          // acquire side
}

// ---------------------------------------------------------------------------
// Kernel 1: g_wx[t,b,e] = alpha * ( sum_d x[t,b,d]*W[e,d] + bias[e] )
// 64x64 tile, 256 threads, 4x4 register tile, fp32.
// ---------------------------------------------------------------------------
__global__ void gemm_wx(const float* __restrict__ X, const float* __restrict__ W,
                        const float* __restrict__ bias, const float* __restrict__ log_alpha)
{
    __shared__ float As[16*68];   // [k][m], padded
    __shared__ float Bs[16*68];   // [k][e], padded

    const int tid = threadIdx.x;
    const int tx  = tid & 15;     // m sub-tile
    const int ty  = tid >> 4;     // e sub-tile
    const int m0  = blockIdx.y * 64;
    const int e0  = blockIdx.x * 64;
    const int r   = tid >> 2;     // 0..63 row within tile
    const int kq  = tid & 3;      // 0..3  float4 column group

    float acc[4][4];
    #pragma unroll
    for (int i = 0; i < 4; i++)
        #pragma unroll
        for (int j = 0; j < 4; j++) acc[i][j] = 0.f;

    for (int k0 = 0; k0 < DIM; k0 += 16) {
        float4 xv = *(const float4*)&X[(size_t)(m0 + r)*DIM + k0 + kq*4];
        float4 wv = *(const float4*)&W[(size_t)(e0 + r)*DIM + k0 + kq*4];
        As[(kq*4+0)*68 + r] = xv.x;  As[(kq*4+1)*68 + r] = xv.y;
        As[(kq*4+2)*68 + r] = xv.z;  As[(kq*4+3)*68 + r] = xv.w;
        Bs[(kq*4+0)*68 + r] = wv.x;  Bs[(kq*4+1)*68 + r] = wv.y;
        Bs[(kq*4+2)*68 + r] = wv.z;  Bs[(kq*4+3)*68 + r] = wv.w;
        __syncthreads();

        #pragma unroll
        for (int kk = 0; kk < 16; kk++) {
            float4 a4 = *(const float4*)&As[kk*68 + tx*4];
            float4 b4 = *(const float4*)&Bs[kk*68 + ty*4];
            float av[4] = {a4.x, a4.y, a4.z, a4.w};
            float bv[4] = {b4.x, b4.y, b4.z, b4.w};
            #pragma unroll
            for (int i = 0; i < 4; i++)
                #pragma unroll
                for (int j = 0; j < 4; j++)
                    acc[i][j] = fmaf(av[i], bv[j], acc[i][j]);
        }
        __syncthreads();
    }

    const float alpha = expf(log_alpha[0]);
    float4 bb = *(const float4*)&bias[e0 + ty*4];
    float bvv[4] = {bb.x, bb.y, bb.z, bb.w};
    #pragma unroll
    for (int i = 0; i < 4; i++) {
        float4 o;
        o.x = alpha*(acc[i][0] + bvv[0]);
        o.y = alpha*(acc[i][1] + bvv[1]);
        o.z = alpha*(acc[i][2] + bvv[2]);
        o.w = alpha*(acc[i][3] + bvv[3]);
        *(float4*)&g_wx[(size_t)(m0 + tx*4 + i)*DIM + e0 + ty*4] = o;
    }
}

// ---------------------------------------------------------------------------
// Kernel 2: persistent recurrence.
// out layout: [outs: T*B*D][h: (T+1)*B*D]
// h_new = rmsnorm(h + alpha*wx + beta*(h @ W_h^T));  out = h_new^2 * sigmoid(h_new)
// CTA c owns e-rows [8c, 8c+8) of W_h in smem. Thread (b=tid>>3, j=tid&7)
// computes one output element per step. 2 grid barriers per step.
// ---------------------------------------------------------------------------
__global__ void recur(const float* __restrict__ h0, const float* __restrict__ W_h,
                      const float* __restrict__ log_beta, float* __restrict__ out)
{
    __shared__ float swh[EPB*WPAD];   // 8 x 1024 W_h rows, padded stride

    float* outs = out;                          // [T][B][D]
    float* hout = out + (size_t)T_STEPS*BD;     // [T+1][B][D]

    const int tid = threadIdx.x;
    const int cta = blockIdx.x;
    const int e0  = cta * EPB;

    // Load this CTA's W_h rows into smem (float4, padded rows: WPAD%4==0)
    for (int i = tid; i < EPB*(DIM/4); i += NTHR) {
        int j  = i >> 8;          // 0..7
        int dq = i & 255;         // float4 index within row
        float4 v = *(const float4*)&W_h[(size_t)(e0 + j)*DIM + dq*4];
        *(float4*)&swh[j*WPAD + dq*4] = v;
    }

    // Cooperative copy h0 -> hout[0]
    {
        int i = cta*NTHR + tid;   // BD/4 = 8192 float4
        if (i < BD/4) ((float4*)hout)[i] = ((const float4*)h0)[i];
    }

    const float beta = 0.1f / (1.0f + expf(-log_beta[0]));
    const int b = tid >> 3;       // 0..31
    const int j = tid & 7;        // 0..7
    const int e = e0 + j;
    const float* wrow = &swh[j*WPAD];

    grid_bar();   // h0 visible everywhere; smem loaded (includes __syncthreads)

    for (int t = 0; t < T_STEPS; t++) {
        const float* hp = hout + (size_t)t*BD + b*DIM;

        // ---- phase A: dot(h_prev[b,:], W_h[e,:]) ----
        float4 acc = make_float4(0.f, 0.f, 0.f, 0.f);
        #pragma unroll 8
        for (int i = 0; i < DIM/4; i++) {
            float4 h4 = ((const float4*)hp)[i];     // LDG: 4 rows/warp, 8-way bcast
            float4 w4 = *(const float4*)&wrow[i*4]; // LDS: 8 distinct quads, conflict-free
            acc.x = fmaf(h4.x, w4.x, acc.x);
            acc.y = fmaf(h4.y, w4.y, acc.y);
            acc.z = fmaf(h4.z, w4.z, acc.z);
            acc.w = fmaf(h4.w, w4.w, acc.w);
        }
        float dot = (acc.x + acc.y) + (acc.z + acc.w);

        float pre = hp[e] + g_wx[(size_t)t*BD + b*DIM + e] + beta*dot;

        // per-CTA partial sumsq over this CTA's 8 e's (octet shuffle reduce)
        float ss = pre*pre;
        ss += __shfl_xor_sync(0xffffffffu, ss, 1);
        ss += __shfl_xor_sync(0xffffffffu, ss, 2);
        ss += __shfl_xor_sync(0xffffffffu, ss, 4);
        if (j == 0) g_part[b*NCTA + cta] = ss;

        grid_bar();   // all partials published

        // ---- phase B: total sumsq, normalize, write outputs ----
        float tot = 0.f;
        #pragma unroll
        for (int c = j; c < NCTA; c += 8)
            tot += __ldcg(&g_part[b*NCTA + c]);   // .cg: bypass (stale) L1
        tot += __shfl_xor_sync(0xffffffffu, tot, 1);
        tot += __shfl_xor_sync(0xffffffffu, tot, 2);
        tot += __shfl_xor_sync(0xffffffffu, tot, 4);

        float rinv = rsqrtf(tot * (1.0f/DIM) + 1e-6f);
        float hn   = pre * rinv;
        float sg   = 1.0f / (1.0f + __expf(-hn));

        hout[(size_t)(t+1)*BD + b*DIM + e] = hn;
        outs[(size_t)t*BD + b*DIM + e]     = hn*hn*sg;

        grid_bar();   // h[t+1] fully visible before next step reads it
    }
}

// ---------------------------------------------------------------------------
extern "C" void kernel_launch(void* const* d_in, const int* in_sizes, int n_in,
                              void* d_out, int out_size) {
    const float* x    = (const float*)d_in[0];  // [512,32,1024]
    const float* h0   = (const float*)d_in[1];  // [32,1024]
    const float* W    = (const float*)d_in[2];  // [1024,1024]
    const float* W_h  = (const float*)d_in[3];  // [1024,1024]
    const float* bias = (const float*)d_in[4];  // [1024]
    const float* la   = (const float*)d_in[5];  // scalar
    const float* lb   = (const float*)d_in[6];  // scalar
    float* out = (float*)d_out;                 // [outs | h] fp32

    dim3 ggrid(DIM/64, (T_STEPS*BATCH)/64);     // (16, 256)
    gemm_wx<<<ggrid, 256>>>(x, W, bias, la);
    recur<<<NCTA, NTHR>>>(h0, W_h, lb, out);
}

// round 4
// speedup vs baseline: 2.8687x; 2.8687x over previous
#include <cuda_runtime.h>
#include <math.h>

// Fixed problem shapes
#define T_STEPS 512
#define BATCH   32
#define DIM     1024
#define BD      (BATCH*DIM)          // 32768
#define NCTA    128                  // all co-resident (<=148 SMs)
#define NTHR    256
#define E_CTA   32                   // e-rows of W_h per CTA
#define B_CTA   8                    // batches per CTA
#define NEG     (DIM/E_CTA)          // 32 e-groups
#define SPAD    1028                 // smem row stride (floats): conflict-free

// Device scratch (allocation-free rule: __device__ globals)
__device__ float    g_wx [(size_t)T_STEPS*BD];      // alpha*(x@W^T)+alpha*b
__device__ float    g_pre[(size_t)(T_STEPS+1)*BD];  // un-normalized h (pre-RMS)
__device__ float    g_part[BATCH*NEG];              // sumsq partials [b][eg]
__device__ unsigned g_cnt;
__device__ volatile unsigned g_gen;

// ---------------------------------------------------------------------------
// packed f32x2 helpers (ptxas never auto-fuses FFMA2 from C++)
// ---------------------------------------------------------------------------
#define FMA2(acc, a, b) \
    asm("fma.rn.f32x2 %0, %1, %2, %0;" : "+l"(acc) : "l"(a), "l"(b))

__device__ __forceinline__ unsigned long long pk2(float x, float y) {
    unsigned long long r;
    asm("mov.b64 %0, {%1,%2};" : "=l"(r)
        : "r"(__float_as_uint(x)), "r"(__float_as_uint(y)));
    return r;
}
__device__ __forceinline__ float2 upk2(unsigned long long v) {
    unsigned lo, hi;
    asm("mov.b64 {%0,%1}, %2;" : "=r"(lo), "=r"(hi) : "l"(v));
    return make_float2(__uint_as_float(lo), __uint_as_float(hi));
}

// ---------------------------------------------------------------------------
// Grid barrier (sense-reversing; all NCTA CTAs resident)
// ---------------------------------------------------------------------------
__device__ __forceinline__ void grid_bar() {
    __threadfence();
    __syncthreads();
    if (threadIdx.x == 0) {
        unsigned gen = g_gen;
        if (atomicAdd(&g_cnt, 1u) == (unsigned)(NCTA - 1)) {
            g_cnt = 0u;
            __threadfence();
            g_gen = gen + 1u;
        } else {
            while (g_gen == gen) { }
        }
    }
    __syncthreads();
    __threadfence();
}

// ---------------------------------------------------------------------------
// Kernel 1: g_wx[t,b,e] = alpha * ( x[t,b,:] . W[e,:] + bias[e] )
// 64x64 tile, 4x4 register tile, FFMA2 inner product.
// ---------------------------------------------------------------------------
__global__ void gemm_wx(const float* __restrict__ X, const float* __restrict__ W,
                        const float* __restrict__ bias, const float* __restrict__ log_alpha)
{
    __shared__ float As[16*68];
    __shared__ float Bs[16*68];

    const int tid = threadIdx.x;
    const int tx  = tid & 15;
    const int ty  = tid >> 4;
    const int m0  = blockIdx.y * 64;
    const int e0  = blockIdx.x * 64;
    const int r   = tid >> 2;
    const int kq  = tid & 3;

    unsigned long long ac[4][2];
    #pragma unroll
    for (int i = 0; i < 4; i++) { ac[i][0] = 0ull; ac[i][1] = 0ull; }

    for (int k0 = 0; k0 < DIM; k0 += 16) {
        float4 xv = *(const float4*)&X[(size_t)(m0 + r)*DIM + k0 + kq*4];
        float4 wv = *(const float4*)&W[(size_t)(e0 + r)*DIM + k0 + kq*4];
        As[(kq*4+0)*68 + r] = xv.x;  As[(kq*4+1)*68 + r] = xv.y;
        As[(kq*4+2)*68 + r] = xv.z;  As[(kq*4+3)*68 + r] = xv.w;
        Bs[(kq*4+0)*68 + r] = wv.x;  Bs[(kq*4+1)*68 + r] = wv.y;
        Bs[(kq*4+2)*68 + r] = wv.z;  Bs[(kq*4+3)*68 + r] = wv.w;
        __syncthreads();

        #pragma unroll
        for (int kk = 0; kk < 16; kk++) {
            float4 a4 = *(const float4*)&As[kk*68 + tx*4];
            // Bs row offset kk*68*4 = kk*272 bytes (16-mult) + ty*16 -> 16B aligned
            ulonglong2 b2 = *(const ulonglong2*)&Bs[kk*68 + ty*4];
            float av[4] = {a4.x, a4.y, a4.z, a4.w};
            #pragma unroll
            for (int i = 0; i < 4; i++) {
                unsigned long long ad = pk2(av[i], av[i]);
                FMA2(ac[i][0], ad, b2.x);
                FMA2(ac[i][1], ad, b2.y);
            }
        }
        __syncthreads();
    }

    const float alpha = expf(log_alpha[0]);
    float4 bb = *(const float4*)&bias[e0 + ty*4];
    #pragma unroll
    for (int i = 0; i < 4; i++) {
        float2 p0 = upk2(ac[i][0]);
        float2 p1 = upk2(ac[i][1]);
        float4 o;
        o.x = alpha*(p0.x + bb.x);
        o.y = alpha*(p0.y + bb.y);
        o.z = alpha*(p1.x + bb.z);
        o.w = alpha*(p1.y + bb.w);
        *(float4*)&g_wx[(size_t)(m0 + tx*4 + i)*DIM + e0 + ty*4] = o;
    }
}

// ---------------------------------------------------------------------------
// Kernel 2: persistent recurrence, deferred normalization, ONE barrier/step.
//
// CTA (eg,bg) owns e in [eg*32, eg*32+32), b in [bg*8, bg*8+8).
// W_h rows pinned in smem (128KB); pre[t] tile (8 rows) staged per step (32KB).
// Thread (w=tid>>5, lane): b = b0 + (lane>>2), e = e0 + w*4 + (lane&3).
//
// Invariant at top of step t: g_pre[t] and g_part (sumsq of pre[t]) published.
//   rinv[t] = rsqrt(mean(pre[t]^2)+eps)   (rinv[0] forced = 1: h0 is raw)
//   h[t]    = rinv[t]*pre[t]
//   pre[t+1][b][e] = h[t][b][e] + wx[t][b][e] + beta*rinv[t]*(pre[t][b,:].W_h[e,:])
// out layout: [outs: T*BD][h: (T+1)*BD]
// ---------------------------------------------------------------------------
#define S_W    0
#define S_H    (E_CTA*SPAD)                  // 32896
#define S_RINV (S_H + B_CTA*SPAD)            // 41120
#define S_SS   (S_RINV + 8)                  // 41128 (8 warps x 8 b)
#define S_TOT  (S_SS + 64)                   // 41192 floats
#define SMEM_BYTES (S_TOT*4)                 // 164768 B

__global__ void __launch_bounds__(NTHR, 1)
recur(const float* __restrict__ h0, const float* __restrict__ W_h,
      const float* __restrict__ log_beta, float* __restrict__ out)
{
    extern __shared__ float sm[];
    float* s_w    = sm + S_W;
    float* s_h    = sm + S_H;
    float* s_rinv = sm + S_RINV;
    float* s_ss   = sm + S_SS;

    float* outs = out;
    float* hout = out + (size_t)T_STEPS*BD;

    const int tid   = threadIdx.x;
    const int w     = tid >> 5;
    const int lane  = tid & 31;
    const int b_l   = lane >> 2;
    const int e_sub = lane & 3;
    const int eg    = blockIdx.x & (NEG-1);
    const int bg    = blockIdx.x >> 5;
    const int e0    = eg * E_CTA;
    const int b0    = bg * B_CTA;
    const int e_l   = w*4 + e_sub;
    const int e     = e0 + e_l;
    const int b     = b0 + b_l;

    const float beta = 0.1f / (1.0f + expf(-log_beta[0]));

    // Pin W_h rows in smem
    for (int i = tid; i < E_CTA*(DIM/4); i += NTHR) {
        int r = i >> 8, q = i & 255;
        float4 v = *(const float4*)&W_h[(size_t)(e0 + r)*DIM + q*4];
        *(float4*)&s_w[r*SPAD + q*4] = v;
    }
    // h0 -> g_pre[0] and hout[0] (raw), sliced across CTAs
    if (tid < 64) {
        int idx = blockIdx.x*64 + tid;               // BD/4 = 8192 float4 total
        float4 v = ((const float4*)h0)[idx];
        ((float4*)g_pre)[idx] = v;
        ((float4*)hout)[idx]  = v;
    }
    // Synthetic partials so rinv[0] == 1 (h0 enters recurrence un-normalized)
    if (tid < B_CTA)
        g_part[(b0 + tid)*NEG + eg] = (float)E_CTA * (1.0f - 1e-6f);

    float pre_self = h0[(size_t)b*DIM + e];

    grid_bar();

    const ulonglong2* wr2 = (const ulonglong2*)&s_w[e_l*SPAD];

    for (int t = 0; t < T_STEPS; t++) {
        // ---- rinv[t]: every warp reduces the 32 partials for its batch ----
        {
            float p = __ldcg(&g_part[(b0 + w)*NEG + lane]);
            p += __shfl_xor_sync(0xffffffffu, p, 16);
            p += __shfl_xor_sync(0xffffffffu, p, 8);
            p += __shfl_xor_sync(0xffffffffu, p, 4);
            p += __shfl_xor_sync(0xffffffffu, p, 2);
            p += __shfl_xor_sync(0xffffffffu, p, 1);
            if (lane == 0)
                s_rinv[w] = rsqrtf(p * (1.0f/DIM) + 1e-6f);
        }
        // ---- stage pre[t] tile (8 rows), fully coalesced ----
        const float* pt = g_pre + (size_t)t*BD;
        for (int i = tid; i < B_CTA*(DIM/4); i += NTHR) {
            int r = i >> 8, q = i & 255;
            float4 v = *(const float4*)&pt[(size_t)(b0 + r)*DIM + q*4];
            *(float4*)&s_h[r*SPAD + q*4] = v;
        }
        float wxv = g_wx[(size_t)t*BD + (size_t)b*DIM + e];
        __syncthreads();

        const float rv = s_rinv[b_l];

        // h[t] element owned by this thread; emit hout[t] (t=0 identical to raw
        // copy since rinv[0]==1) and outs[t-1] = h[t]*silu(h[t])
        float hn = rv * pre_self;
        hout[(size_t)t*BD + (size_t)b*DIM + e] = hn;
        if (t > 0) {
            float sg = 1.0f / (1.0f + __expf(-hn));
            outs[(size_t)(t-1)*BD + (size_t)b*DIM + e] = hn*hn*sg;
        }

        // ---- dot(pre[t][b,:], W_h[e,:]) from smem, 4 FFMA2 chains ----
        const ulonglong2* hr2 = (const ulonglong2*)&s_h[b_l*SPAD];
        unsigned long long a0 = 0ull, a1 = 0ull, a2 = 0ull, a3 = 0ull;
        #pragma unroll 8
        for (int q = 0; q < 256; q += 2) {
            ulonglong2 hv0 = hr2[q],   wv0 = wr2[q];
            ulonglong2 hv1 = hr2[q+1], wv1 = wr2[q+1];
            FMA2(a0, hv0.x, wv0.x);
            FMA2(a1, hv0.y, wv0.y);
            FMA2(a2, hv1.x, wv1.x);
            FMA2(a3, hv1.y, wv1.y);
        }
        float2 f0 = upk2(a0), f1 = upk2(a1), f2 = upk2(a2), f3 = upk2(a3);
        float dot = ((f0.x + f0.y) + (f1.x + f1.y))
                  + ((f2.x + f2.y) + (f3.x + f3.y));

        float pre_new = hn + wxv + beta * rv * dot;
        g_pre[(size_t)(t+1)*BD + (size_t)b*DIM + e] = pre_new;

        // ---- sumsq partial for this CTA's 32 e's, per batch ----
        float ss = pre_new * pre_new;
        ss += __shfl_xor_sync(0xffffffffu, ss, 1);
        ss += __shfl_xor_sync(0xffffffffu, ss, 2);
        if (e_sub == 0) s_ss[w*8 + b_l] = ss;
        __syncthreads();
        if (w == 0) {
            int k  = lane >> 3;          // 0..3
            int bb = lane & 7;
            float v = s_ss[k*8 + bb] + s_ss[(k+4)*8 + bb];
            v += __shfl_xor_sync(0xffffffffu, v, 8);
            v += __shfl_xor_sync(0xffffffffu, v, 16);
            if (lane < 8)
                g_part[(b0 + lane)*NEG + eg] = v;
        }
        pre_self = pre_new;

        grid_bar();   // the ONLY barrier per step
    }

    // ---- epilogue: rinv[T] -> hout[T], outs[T-1] ----
    {
        float p = __ldcg(&g_part[(b0 + w)*NEG + lane]);
        p += __shfl_xor_sync(0xffffffffu, p, 16);
        p += __shfl_xor_sync(0xffffffffu, p, 8);
        p += __shfl_xor_sync(0xffffffffu, p, 4);
        p += __shfl_xor_sync(0xffffffffu, p, 2);
        p += __shfl_xor_sync(0xffffffffu, p, 1);
        if (lane == 0)
            s_rinv[w] = rsqrtf(p * (1.0f/DIM) + 1e-6f);
        __syncthreads();
        float rv = s_rinv[b_l];
        float hn = rv * pre_self;
        hout[(size_t)T_STEPS*BD + (size_t)b*DIM + e] = hn;
        float sg = 1.0f / (1.0f + __expf(-hn));
        outs[(size_t)(T_STEPS-1)*BD + (size_t)b*DIM + e] = hn*hn*sg;
    }
}

// ---------------------------------------------------------------------------
extern "C" void kernel_launch(void* const* d_in, const int* in_sizes, int n_in,
                              void* d_out, int out_size) {
    const float* x    = (const float*)d_in[0];
    const float* h0   = (const float*)d_in[1];
    const float* W    = (const float*)d_in[2];
    const float* W_h  = (const float*)d_in[3];
    const float* bias = (const float*)d_in[4];
    const float* la   = (const float*)d_in[5];
    const float* lb   = (const float*)d_in[6];
    float* out = (float*)d_out;

    static int configured = 0;
    if (!configured) {
        cudaFuncSetAttribute(recur, cudaFuncAttributeMaxDynamicSharedMemorySize,
                             SMEM_BYTES);
        configured = 1;
    }

    dim3 ggrid(DIM/64, (T_STEPS*BATCH)/64);
    gemm_wx<<<ggrid, 256>>>(x, W, bias, la);
    recur<<<NCTA, NTHR, SMEM_BYTES>>>(h0, W_h, lb, out);
}

// round 5
// speedup vs baseline: 3.1825x; 1.1094x over previous
#include <cuda_runtime.h>
#include <math.h>

// Fixed problem shapes
#define T_STEPS 512
#define BATCH   32
#define DIM     1024
#define BD      (BATCH*DIM)          // 32768
#define NCTA    128                  // all co-resident (<=148 SMs)
#define NTHR    512                  // 16 warps: split-K over the dot
#define E_CTA   32                   // e-rows of W_h per CTA
#define B_CTA   8                    // batches per CTA
#define NEG     (DIM/E_CTA)          // 32 e-groups
#define SPAD    1028                 // smem row stride (floats): conflict-free

// Device scratch (allocation-free rule)
__device__ float    g_wx [(size_t)T_STEPS*BD];
__device__ float    g_pre[(size_t)(T_STEPS+1)*BD];
__device__ float    g_part[BATCH*NEG];
__device__ unsigned g_cnt;
__device__ volatile unsigned g_gen;

// ---------------------------------------------------------------------------
// packed f32x2 helpers (ptxas never fuses FFMA2 from C++)
// ---------------------------------------------------------------------------
#define FMA2(acc, a, b) \
    asm("fma.rn.f32x2 %0, %1, %2, %0;" : "+l"(acc) : "l"(a), "l"(b))

__device__ __forceinline__ unsigned long long pk2(float x, float y) {
    unsigned long long r;
    asm("mov.b64 %0, {%1,%2};" : "=l"(r)
        : "r"(__float_as_uint(x)), "r"(__float_as_uint(y)));
    return r;
}
__device__ __forceinline__ float2 upk2(unsigned long long v) {
    unsigned lo, hi;
    asm("mov.b64 {%0,%1}, %2;" : "=r"(lo), "=r"(hi) : "l"(v));
    return make_float2(__uint_as_float(lo), __uint_as_float(hi));
}

// cp.async 16B (LDGSTS): no register round-trip for staging
__device__ __forceinline__ void cpasync16(float* dst, const float* src) {
    unsigned ds = (unsigned)__cvta_generic_to_shared(dst);
    asm volatile("cp.async.ca.shared.global [%0], [%1], 16;" :: "r"(ds), "l"(src));
}
#define CP_COMMIT() asm volatile("cp.async.commit_group;")
#define CP_WAIT0()  asm volatile("cp.async.wait_group 0;" ::: "memory")

// ---------------------------------------------------------------------------
// Grid barrier (sense-reversing; all NCTA CTAs resident)
// ---------------------------------------------------------------------------
__device__ __forceinline__ void grid_bar() {
    __threadfence();
    __syncthreads();
    if (threadIdx.x == 0) {
        unsigned gen = g_gen;
        if (atomicAdd(&g_cnt, 1u) == (unsigned)(NCTA - 1)) {
            g_cnt = 0u;
            __threadfence();
            g_gen = gen + 1u;
        } else {
            while (g_gen == gen) { }
        }
    }
    __syncthreads();
    __threadfence();
}

// ---------------------------------------------------------------------------
// Kernel 1: g_wx[t,b,e] = alpha*(x[t,b,:].W[e,:] + bias[e])
// 128x128 tile, 256 threads, 8x8 register tile, double-buffered, FFMA2.
// ---------------------------------------------------------------------------
__global__ void __launch_bounds__(256)
gemm_wx(const float* __restrict__ X, const float* __restrict__ W,
        const float* __restrict__ bias, const float* __restrict__ log_alpha)
{
    __shared__ float As[2][8][136];   // [buf][k][m], 136-stride: 16B-aligned rows
    __shared__ float Bs[2][8][136];   // [buf][k][e]

    const int tid = threadIdx.x;
    const int tx  = tid & 15;         // m sub-tile (x4, two halves)
    const int ty  = tid >> 4;         // e sub-tile
    const int m0  = blockIdx.y * 128;
    const int e0  = blockIdx.x * 128;
    const int lr  = tid >> 1;         // 0..127 load row
    const int lc  = (tid & 1) * 4;    // k column group

    unsigned long long ac[8][4];
    #pragma unroll
    for (int i = 0; i < 8; i++)
        #pragma unroll
        for (int j = 0; j < 4; j++) ac[i][j] = 0ull;

    // preload stage 0
    {
        float4 av = *(const float4*)&X[(size_t)(m0 + lr)*DIM + lc];
        float4 bv = *(const float4*)&W[(size_t)(e0 + lr)*DIM + lc];
        As[0][lc+0][lr] = av.x; As[0][lc+1][lr] = av.y;
        As[0][lc+2][lr] = av.z; As[0][lc+3][lr] = av.w;
        Bs[0][lc+0][lr] = bv.x; Bs[0][lc+1][lr] = bv.y;
        Bs[0][lc+2][lr] = bv.z; Bs[0][lc+3][lr] = bv.w;
    }
    __syncthreads();

    for (int k0 = 0; k0 < DIM; k0 += 8) {
        const int buf  = (k0 >> 3) & 1;
        const int nbuf = buf ^ 1;
        float4 av, bv;
        const bool more = (k0 + 8) < DIM;
        if (more) {
            av = *(const float4*)&X[(size_t)(m0 + lr)*DIM + k0 + 8 + lc];
            bv = *(const float4*)&W[(size_t)(e0 + lr)*DIM + k0 + 8 + lc];
        }

        #pragma unroll
        for (int kk = 0; kk < 8; kk++) {
            float4 a0 = *(const float4*)&As[buf][kk][tx*4];
            float4 a1 = *(const float4*)&As[buf][kk][tx*4 + 64];
            ulonglong2 b0 = *(const ulonglong2*)&Bs[buf][kk][ty*4];
            ulonglong2 b1 = *(const ulonglong2*)&Bs[buf][kk][ty*4 + 64];
            float am[8] = {a0.x,a0.y,a0.z,a0.w, a1.x,a1.y,a1.z,a1.w};
            #pragma unroll
            for (int i = 0; i < 8; i++) {
                unsigned long long ad = pk2(am[i], am[i]);
                FMA2(ac[i][0], ad, b0.x);
                FMA2(ac[i][1], ad, b0.y);
                FMA2(ac[i][2], ad, b1.x);
                FMA2(ac[i][3], ad, b1.y);
            }
        }

        if (more) {
            As[nbuf][lc+0][lr] = av.x; As[nbuf][lc+1][lr] = av.y;
            As[nbuf][lc+2][lr] = av.z; As[nbuf][lc+3][lr] = av.w;
            Bs[nbuf][lc+0][lr] = bv.x; Bs[nbuf][lc+1][lr] = bv.y;
            Bs[nbuf][lc+2][lr] = bv.z; Bs[nbuf][lc+3][lr] = bv.w;
        }
        __syncthreads();
    }

    const float alpha = expf(log_alpha[0]);
    float4 bb0 = *(const float4*)&bias[e0 + ty*4];
    float4 bb1 = *(const float4*)&bias[e0 + ty*4 + 64];
    #pragma unroll
    for (int i = 0; i < 8; i++) {
        int m = m0 + ((i < 4) ? (tx*4 + i) : (64 + tx*4 + i - 4));
        float2 p0 = upk2(ac[i][0]);
        float2 p1 = upk2(ac[i][1]);
        float2 p2 = upk2(ac[i][2]);
        float2 p3 = upk2(ac[i][3]);
        float4 o0, o1;
        o0.x = alpha*(p0.x + bb0.x); o0.y = alpha*(p0.y + bb0.y);
        o0.z = alpha*(p1.x + bb0.z); o0.w = alpha*(p1.y + bb0.w);
        o1.x = alpha*(p2.x + bb1.x); o1.y = alpha*(p2.y + bb1.y);
        o1.z = alpha*(p3.x + bb1.z); o1.w = alpha*(p3.y + bb1.w);
        *(float4*)&g_wx[(size_t)m*DIM + e0 + ty*4]      = o0;
        *(float4*)&g_wx[(size_t)m*DIM + e0 + ty*4 + 64] = o1;
    }
}

// ---------------------------------------------------------------------------
// Kernel 2: persistent recurrence, split-K, deferred normalization,
// one grid barrier per step.
//
// CTA (eg,bg): e in [eg*32,+32), b in [bg*8,+8). 512 threads:
//   warp w: kh = w>>3 (K half), w8 = w&7; lane: b_l=lane>>2, e_sub=lane&3
//   thread computes half-dot for (b = b0+b_l, e = e0+w8*4+e_sub).
// Halves combined through s_red. All other invariants as R4:
//   rinv[t]=rsqrt(mean(pre^2)+eps) (rinv[0]==1 via synthetic partials),
//   pre[t+1] = rinv*pre + wx + beta*rinv*(pre[t].W_h^T row)
// ---------------------------------------------------------------------------
#define S_W    0
#define S_H    (E_CTA*SPAD)                   // 32896
#define S_RINV (S_H + B_CTA*SPAD)             // +8224
#define S_SS   (S_RINV + 8)
#define S_RED  (S_SS + 64)
#define S_TOT  (S_RED + 256)
#define SMEM_BYTES (S_TOT*4)

__global__ void __launch_bounds__(NTHR, 1)
recur(const float* __restrict__ h0, const float* __restrict__ W_h,
      const float* __restrict__ log_beta, float* __restrict__ out)
{
    extern __shared__ float sm[];
    float* s_w    = sm + S_W;
    float* s_h    = sm + S_H;
    float* s_rinv = sm + S_RINV;
    float* s_ss   = sm + S_SS;
    float* s_red  = sm + S_RED;

    float* outs = out;
    float* hout = out + (size_t)T_STEPS*BD;

    const int tid   = threadIdx.x;
    const int w     = tid >> 5;
    const int lane  = tid & 31;
    const int kh    = w >> 3;        // K half: 0/1
    const int w8    = w & 7;
    const int b_l   = lane >> 2;
    const int e_sub = lane & 3;
    const int eg    = blockIdx.x & (NEG-1);
    const int bg    = blockIdx.x >> 5;
    const int e0    = eg * E_CTA;
    const int b0    = bg * B_CTA;
    const int e_l   = w8*4 + e_sub;
    const int e     = e0 + e_l;
    const int b     = b0 + b_l;

    const float beta = 0.1f / (1.0f + expf(-log_beta[0]));

    // Pin W_h rows in smem
    for (int i = tid; i < E_CTA*(DIM/4); i += NTHR) {
        int r = i >> 8, q = i & 255;
        float4 v = *(const float4*)&W_h[(size_t)(e0 + r)*DIM + q*4];
        *(float4*)&s_w[r*SPAD + q*4] = v;
    }
    // h0 -> g_pre[0] and hout[0] (raw), sliced across CTAs
    if (tid < 64) {
        int idx = blockIdx.x*64 + tid;
        float4 v = ((const float4*)h0)[idx];
        ((float4*)g_pre)[idx] = v;
        ((float4*)hout)[idx]  = v;
    }
    // Synthetic partials so rinv[0] == 1
    if (tid < B_CTA)
        g_part[(b0 + tid)*NEG + eg] = (float)E_CTA * (1.0f - 1e-6f);

    float pre_self = h0[(size_t)b*DIM + e];

    grid_bar();

    const ulonglong2* wr2 = (const ulonglong2*)&s_w[e_l*SPAD] + (kh << 7);

    for (int t = 0; t < T_STEPS; t++) {
        // wx prefetch (independent of everything in this step)
        float wxv = __ldg(&g_wx[(size_t)t*BD + (size_t)b*DIM + e]);

        // stage pre[t] tile (8 contiguous rows = 32KB) via cp.async
        {
            const float* pt = g_pre + (size_t)t*BD + (size_t)b0*DIM;
            #pragma unroll
            for (int j = 0; j < 4; j++) {
                int idx = j*NTHR + tid;          // 0..2047 float4
                int r = idx >> 8, q = idx & 255;
                cpasync16(&s_h[r*SPAD + q*4], pt + idx*4);
            }
            CP_COMMIT();
        }
        // rinv[t]: warps 0..7 reduce the 32 partials for their batch
        if (w < 8) {
            float p = __ldcg(&g_part[(b0 + w)*NEG + lane]);
            p += __shfl_xor_sync(0xffffffffu, p, 16);
            p += __shfl_xor_sync(0xffffffffu, p, 8);
            p += __shfl_xor_sync(0xffffffffu, p, 4);
            p += __shfl_xor_sync(0xffffffffu, p, 2);
            p += __shfl_xor_sync(0xffffffffu, p, 1);
            if (lane == 0)
                s_rinv[w] = rsqrtf(p * (1.0f/DIM) + 1e-6f);
        }
        CP_WAIT0();
        __syncthreads();   // s_h + s_rinv visible

        // half-dot over 512 dims: 4 FFMA2 chains
        const ulonglong2* hr2 = (const ulonglong2*)&s_h[b_l*SPAD] + (kh << 7);
        unsigned long long a0 = 0ull, a1 = 0ull, a2 = 0ull, a3 = 0ull;
        #pragma unroll 8
        for (int q = 0; q < 128; q += 2) {
            ulonglong2 hv0 = hr2[q],   wv0 = wr2[q];
            ulonglong2 hv1 = hr2[q+1], wv1 = wr2[q+1];
            FMA2(a0, hv0.x, wv0.x);
            FMA2(a1, hv0.y, wv0.y);
            FMA2(a2, hv1.x, wv1.x);
            FMA2(a3, hv1.y, wv1.y);
        }
        float2 f0 = upk2(a0), f1 = upk2(a1), f2 = upk2(a2), f3 = upk2(a3);
        float partial = ((f0.x + f0.y) + (f1.x + f1.y))
                      + ((f2.x + f2.y) + (f3.x + f3.y));

        if (kh == 1) s_red[tid - 256] = partial;
        __syncthreads();

        if (kh == 0) {
            const float rv  = s_rinv[b_l];
            const float dot = partial + s_red[tid];

            float hn = rv * pre_self;
            hout[(size_t)t*BD + (size_t)b*DIM + e] = hn;
            if (t > 0) {
                float sg = 1.0f / (1.0f + __expf(-hn));
                outs[(size_t)(t-1)*BD + (size_t)b*DIM + e] = hn*hn*sg;
            }

            float pre_new = hn + wxv + beta * rv * dot;
            g_pre[(size_t)(t+1)*BD + (size_t)b*DIM + e] = pre_new;

            float ss = pre_new * pre_new;
            ss += __shfl_xor_sync(0xffffffffu, ss, 1);
            ss += __shfl_xor_sync(0xffffffffu, ss, 2);
            if (e_sub == 0) s_ss[w8*8 + b_l] = ss;
            pre_self = pre_new;
        }
        __syncthreads();
        if (w == 0) {   // warp 0 is a kh==0 warp
            int k  = lane >> 3;
            int bb = lane & 7;
            float v = s_ss[k*8 + bb] + s_ss[(k+4)*8 + bb];
            v += __shfl_xor_sync(0xffffffffu, v, 8);
            v += __shfl_xor_sync(0xffffffffu, v, 16);
            if (lane < 8)
                g_part[(b0 + lane)*NEG + eg] = v;
        }

        grid_bar();   // the only grid barrier per step
    }

    // epilogue: rinv[T] -> hout[T], outs[T-1]
    if (w < 8) {
        float p = __ldcg(&g_part[(b0 + w)*NEG + lane]);
        p += __shfl_xor_sync(0xffffffffu, p, 16);
        p += __shfl_xor_sync(0xffffffffu, p, 8);
        p += __shfl_xor_sync(0xffffffffu, p, 4);
        p += __shfl_xor_sync(0xffffffffu, p, 2);
        p += __shfl_xor_sync(0xffffffffu, p, 1);
        if (lane == 0)
            s_rinv[w] = rsqrtf(p * (1.0f/DIM) + 1e-6f);
    }
    __syncthreads();
    if (kh == 0) {
        float rv = s_rinv[b_l];
        float hn = rv * pre_self;
        hout[(size_t)T_STEPS*BD + (size_t)b*DIM + e] = hn;
        float sg = 1.0f / (1.0f + __expf(-hn));
        outs[(size_t)(T_STEPS-1)*BD + (size_t)b*DIM + e] = hn*hn*sg;
    }
}

// ---------------------------------------------------------------------------
extern "C" void kernel_launch(void* const* d_in, const int* in_sizes, int n_in,
                              void* d_out, int out_size) {
    const float* x    = (const float*)d_in[0];
    const float* h0   = (const float*)d_in[1];
    const float* W    = (const float*)d_in[2];
    const float* W_h  = (const float*)d_in[3];
    const float* bias = (const float*)d_in[4];
    const float* la   = (const float*)d_in[5];
    const float* lb   = (const float*)d_in[6];
    float* out = (float*)d_out;

    static int configured = 0;
    if (!configured) {
        cudaFuncSetAttribute(recur, cudaFuncAttributeMaxDynamicSharedMemorySize,
                             SMEM_BYTES);
        configured = 1;
    }

    dim3 ggrid(DIM/128, (T_STEPS*BATCH)/128);   // (8, 128)
    gemm_wx<<<ggrid, 256>>>(x, W, bias, la);
    recur<<<NCTA, NTHR, SMEM_BYTES>>>(h0, W_h, lb, out);
}

// round 7
// speedup vs baseline: 5.1025x; 1.6033x over previous
#include <cuda_runtime.h>
#include <cuda_bf16.h>
#include <math.h>

// Fixed problem shapes
#define T_STEPS 512
#define BATCH   32
#define DIM     1024
#define BD      (BATCH*DIM)          // 32768
#define NCTA    128                  // 32 e-groups x 4 b-groups, all co-resident
#define NTHR    512                  // 16 warps
#define E_CTA   32                   // e-rows of W_h per CTA (== warp lanes)
#define B_CTA   8                    // batches per CTA
#define NEG     32                   // e-groups
#define WSTR    1032                 // bf16 elems per smem W row (2064B = 16*129: conflict-free)

// Device scratch (allocation-free rule)
__device__ float         g_wx [(size_t)T_STEPS*BD];        // alpha*(x@W^T)+alpha*b (fp32)
__device__ __nv_bfloat16 g_hbf[(size_t)(T_STEPS+1)*BD];    // un-normalized pre, bf16
__device__ float         g_part[BATCH*NEG];                // sumsq partials [b][eg]
__device__ unsigned      g_cnt;
__device__ volatile unsigned g_gen;

// ---------------------------------------------------------------------------
// helpers
// ---------------------------------------------------------------------------
#define FMA2(acc, a, b) \
    asm("fma.rn.f32x2 %0, %1, %2, %0;" : "+l"(acc) : "l"(a), "l"(b))

__device__ __forceinline__ unsigned long long pk2(float x, float y) {
    unsigned long long r;
    asm("mov.b64 %0, {%1,%2};" : "=l"(r)
        : "r"(__float_as_uint(x)), "r"(__float_as_uint(y)));
    return r;
}
__device__ __forceinline__ float2 upk2(unsigned long long v) {
    unsigned lo, hi;
    asm("mov.b64 {%0,%1}, %2;" : "=r"(lo), "=r"(hi) : "l"(v));
    return make_float2(__uint_as_float(lo), __uint_as_float(hi));
}
__device__ __forceinline__ __nv_bfloat162 u2b(unsigned u) {
    return *reinterpret_cast<__nv_bfloat162*>(&u);
}
// acc += dot of 4 packed bf16x2 words (8 dims)
__device__ __forceinline__ void dot8(__nv_bfloat162& a, uint4 h, uint4 wv) {
    a = __hfma2(u2b(h.x), u2b(wv.x), a);
    a = __hfma2(u2b(h.y), u2b(wv.y), a);
    a = __hfma2(u2b(h.z), u2b(wv.z), a);
    a = __hfma2(u2b(h.w), u2b(wv.w), a);
}

// ---------------------------------------------------------------------------
// Grid barrier (sense-reversing; all NCTA CTAs resident)
// ---------------------------------------------------------------------------
__device__ __forceinline__ void grid_bar() {
    __threadfence();
    __syncthreads();
    if (threadIdx.x == 0) {
        unsigned gen = g_gen;
        if (atomicAdd(&g_cnt, 1u) == (unsigned)(NCTA - 1)) {
            g_cnt = 0u;
            __threadfence();
            g_gen = gen + 1u;
        } else {
            while (g_gen == gen) { }
        }
    }
    __syncthreads();
    __threadfence();
}

// ---------------------------------------------------------------------------
// Kernel 1: g_wx[t,b,e] = alpha*(x[t,b,:].W[e,:] + bias[e])   (fp32, FFMA2)
// 128x128 tile, 256 threads, 8x8 register tile, double-buffered.
// ---------------------------------------------------------------------------
__global__ void __launch_bounds__(256)
gemm_wx(const float* __restrict__ X, const float* __restrict__ W,
        const float* __restrict__ bias, const float* __restrict__ log_alpha)
{
    __shared__ float As[2][8][136];
    __shared__ float Bs[2][8][136];

    const int tid = threadIdx.x;
    const int tx  = tid & 15;
    const int ty  = tid >> 4;
    const int m0  = blockIdx.y * 128;
    const int e0  = blockIdx.x * 128;
    const int lr  = tid >> 1;
    const int lc  = (tid & 1) * 4;

    unsigned long long ac[8][4];
    #pragma unroll
    for (int i = 0; i < 8; i++)
        #pragma unroll
        for (int j = 0; j < 4; j++) ac[i][j] = 0ull;

    {
        float4 av = *(const float4*)&X[(size_t)(m0 + lr)*DIM + lc];
        float4 bv = *(const float4*)&W[(size_t)(e0 + lr)*DIM + lc];
        As[0][lc+0][lr] = av.x; As[0][lc+1][lr] = av.y;
        As[0][lc+2][lr] = av.z; As[0][lc+3][lr] = av.w;
        Bs[0][lc+0][lr] = bv.x; Bs[0][lc+1][lr] = bv.y;
        Bs[0][lc+2][lr] = bv.z; Bs[0][lc+3][lr] = bv.w;
    }
    __syncthreads();

    for (int k0 = 0; k0 < DIM; k0 += 8) {
        const int buf  = (k0 >> 3) & 1;
        const int nbuf = buf ^ 1;
        float4 av, bv;
        const bool more = (k0 + 8) < DIM;
        if (more) {
            av = *(const float4*)&X[(size_t)(m0 + lr)*DIM + k0 + 8 + lc];
            bv = *(const float4*)&W[(size_t)(e0 + lr)*DIM + k0 + 8 + lc];
        }
        #pragma unroll
        for (int kk = 0; kk < 8; kk++) {
            float4 a0 = *(const float4*)&As[buf][kk][tx*4];
            float4 a1 = *(const float4*)&As[buf][kk][tx*4 + 64];
            ulonglong2 b0 = *(const ulonglong2*)&Bs[buf][kk][ty*4];
            ulonglong2 b1 = *(const ulonglong2*)&Bs[buf][kk][ty*4 + 64];
            float am[8] = {a0.x,a0.y,a0.z,a0.w, a1.x,a1.y,a1.z,a1.w};
            #pragma unroll
            for (int i = 0; i < 8; i++) {
                unsigned long long ad = pk2(am[i], am[i]);
                FMA2(ac[i][0], ad, b0.x);
                FMA2(ac[i][1], ad, b0.y);
                FMA2(ac[i][2], ad, b1.x);
                FMA2(ac[i][3], ad, b1.y);
            }
        }
        if (more) {
            As[nbuf][lc+0][lr] = av.x; As[nbuf][lc+1][lr] = av.y;
            As[nbuf][lc+2][lr] = av.z; As[nbuf][lc+3][lr] = av.w;
            Bs[nbuf][lc+0][lr] = bv.x; Bs[nbuf][lc+1][lr] = bv.y;
            Bs[nbuf][lc+2][lr] = bv.z; Bs[nbuf][lc+3][lr] = bv.w;
        }
        __syncthreads();
    }

    const float alpha = expf(log_alpha[0]);
    float4 bb0 = *(const float4*)&bias[e0 + ty*4];
    float4 bb1 = *(const float4*)&bias[e0 + ty*4 + 64];
    #pragma unroll
    for (int i = 0; i < 8; i++) {
        int m = m0 + ((i < 4) ? (tx*4 + i) : (64 + tx*4 + i - 4));
        float2 p0 = upk2(ac[i][0]);
        float2 p1 = upk2(ac[i][1]);
        float2 p2 = upk2(ac[i][2]);
        float2 p3 = upk2(ac[i][3]);
        float4 o0, o1;
        o0.x = alpha*(p0.x + bb0.x); o0.y = alpha*(p0.y + bb0.y);
        o0.z = alpha*(p1.x + bb0.z); o0.w = alpha*(p1.y + bb0.w);
        o1.x = alpha*(p2.x + bb1.x); o1.y = alpha*(p2.y + bb1.y);
        o1.z = alpha*(p3.x + bb1.z); o1.w = alpha*(p3.y + bb1.w);
        *(float4*)&g_wx[(size_t)m*DIM + e0 + ty*4]      = o0;
        *(float4*)&g_wx[(size_t)m*DIM + e0 + ty*4 + 64] = o1;
    }
}

// ---------------------------------------------------------------------------
// Kernel 2: persistent recurrence, bf16 GEMV, one grid barrier per step.
//
// CTA (eg = bid&31, bg = bid>>5): e in [eg*32,+32), b in [bg*8,+8).
// Compute role (all 16 warps): bg2 = w&1 (4 b-rows), ks = w>>1 (128-dim K slice);
//   lane = e. Per 8-dim chunk: 4 uniform LDG.128 (h bf16 broadcast) +
//   1 LDS.128 (W_h bf16 row, conflict-free) + 16 HFMA2.
// Owner role (warps 0-7): b = b0+w, lane = e. Reduces K partials from smem,
//   computes rinv (full-butterfly over 32 eg partials), h, silu, publishes
//   bf16 pre[t+1] and sumsq partial.
// ---------------------------------------------------------------------------
#define SW_BYTES  (E_CTA*WSTR*2)              // 66048
#define SRED_OFF  SW_BYTES
#define SMEM_BYTES (SW_BYTES + 8*B_CTA*E_CTA*4)   // + 8KB partials = 74240

__global__ void __launch_bounds__(NTHR, 1)
recur(const float* __restrict__ h0, const float* __restrict__ W_h,
      const float* __restrict__ log_beta, float* __restrict__ out)
{
    extern __shared__ char smraw[];
    __nv_bfloat16* s_w  = (__nv_bfloat16*)smraw;
    float*         s_red = (float*)(smraw + SRED_OFF);   // [ks 8][b_l 8][e 32]

    float* outs = out;
    float* hout = out + (size_t)T_STEPS*BD;

    const int tid  = threadIdx.x;
    const int w    = tid >> 5;
    const int lane = tid & 31;
    const int eg   = blockIdx.x & 31;
    const int bg   = blockIdx.x >> 5;
    const int e0   = eg * E_CTA;
    const int b0   = bg * B_CTA;
    const int bg2  = w & 1;          // which 4 of the 8 b's
    const int ks   = w >> 1;         // K slice (128 dims)

    const float beta = 0.1f / (1.0f + expf(-log_beta[0]));

    // Pin W_h rows (bf16) in smem, conflict-free padded stride
    for (int i = tid; i < E_CTA*(DIM/4); i += NTHR) {
        int r = i >> 8, q = i & 255;
        float4 v = *(const float4*)&W_h[(size_t)(e0 + r)*DIM + q*4];
        __nv_bfloat162 p0 = __floats2bfloat162_rn(v.x, v.y);
        __nv_bfloat162 p1 = __floats2bfloat162_rn(v.z, v.w);
        *(__nv_bfloat162*)&s_w[r*WSTR + q*4]     = p0;
        *(__nv_bfloat162*)&s_w[r*WSTR + q*4 + 2] = p1;
    }
    // h0 -> g_hbf[0] (bf16), sliced across CTAs
    if (tid < 64) {
        int i = blockIdx.x*64 + tid;               // 8192 float4 total
        float4 v = ((const float4*)h0)[i];
        __nv_bfloat162 p0 = __floats2bfloat162_rn(v.x, v.y);
        __nv_bfloat162 p1 = __floats2bfloat162_rn(v.z, v.w);
        *(__nv_bfloat162*)&g_hbf[(size_t)i*4]     = p0;
        *(__nv_bfloat162*)&g_hbf[(size_t)i*4 + 2] = p1;
    }
    // Synthetic partials so rinv[0] == 1 (h0 enters un-normalized)
    if (tid < B_CTA)
        g_part[(b0 + tid)*NEG + eg] = (float)E_CTA * (1.0f - 1e-6f);

    // owner state (warps 0-7): pre_self in fp32
    float pre_self = 0.f;
    if (w < 8) pre_self = h0[(size_t)(b0 + w)*DIM + e0 + lane];

    grid_bar();

    const uint4* wrow = (const uint4*)((const char*)s_w + lane*(WSTR*2) + ks*256);

    for (int t = 0; t < T_STEPS; t++) {
        // ---- owner prefetch: wx + rinv[t] (full butterfly: all lanes get rv)
        float wxv = 0.f, rv = 0.f;
        if (w < 8) {
            wxv = __ldg(&g_wx[(size_t)t*BD + (size_t)(b0 + w)*DIM + e0 + lane]);
            float p = __ldcg(&g_part[(b0 + w)*NEG + lane]);
            p += __shfl_xor_sync(0xffffffffu, p, 16);
            p += __shfl_xor_sync(0xffffffffu, p, 8);
            p += __shfl_xor_sync(0xffffffffu, p, 4);
            p += __shfl_xor_sync(0xffffffffu, p, 2);
            p += __shfl_xor_sync(0xffffffffu, p, 1);
            rv = rsqrtf(p * (1.0f/DIM) + 1e-6f);
        }

        // ---- compute: 4b x 32e x 128k partial dots (bf16, HFMA2) ----
        const __nv_bfloat16* hp =
            g_hbf + (size_t)t*BD + (size_t)(b0 + bg2*4)*DIM + ks*128;
        __nv_bfloat162 a0 = u2b(0u), a1 = u2b(0u), a2 = u2b(0u), a3 = u2b(0u);
        #pragma unroll
        for (int c = 0; c < 16; c++) {
            uint4 wv  = wrow[c];
            uint4 h0v = *(const uint4*)(hp + 0*DIM + c*8);   // uniform: bcast
            uint4 h1v = *(const uint4*)(hp + 1*DIM + c*8);
            uint4 h2v = *(const uint4*)(hp + 2*DIM + c*8);
            uint4 h3v = *(const uint4*)(hp + 3*DIM + c*8);
            dot8(a0, h0v, wv);
            dot8(a1, h1v, wv);
            dot8(a2, h2v, wv);
            dot8(a3, h3v, wv);
        }
        {
            float2 f0 = __bfloat1622float2(a0);
            float2 f1 = __bfloat1622float2(a1);
            float2 f2 = __bfloat1622float2(a2);
            float2 f3 = __bfloat1622float2(a3);
            int base = ks*256 + bg2*4*32 + lane;
            s_red[base]      = f0.x + f0.y;
            s_red[base + 32] = f1.x + f1.y;
            s_red[base + 64] = f2.x + f2.y;
            s_red[base + 96] = f3.x + f3.y;
        }
        __syncthreads();

        // ---- owner update ----
        if (w < 8) {
            float dot = 0.f;
            #pragma unroll
            for (int k = 0; k < 8; k++)
                dot += s_red[k*256 + w*32 + lane];

            float hn = rv * pre_self;
            size_t o = (size_t)t*BD + (size_t)(b0 + w)*DIM + e0 + lane;
            hout[o] = hn;
            if (t > 0) {
                float sg = 1.0f / (1.0f + __expf(-hn));
                outs[o - BD] = hn*hn*sg;
            }
            float pre_new = hn + wxv + beta * rv * dot;
            g_hbf[o + BD] = __float2bfloat16(pre_new);

            float ss = pre_new * pre_new;
            ss += __shfl_xor_sync(0xffffffffu, ss, 16);
            ss += __shfl_xor_sync(0xffffffffu, ss, 8);
            ss += __shfl_xor_sync(0xffffffffu, ss, 4);
            ss += __shfl_xor_sync(0xffffffffu, ss, 2);
            ss += __shfl_xor_sync(0xffffffffu, ss, 1);
            if (lane == 0) g_part[(b0 + w)*NEG + eg] = ss;
            pre_self = pre_new;
        }

        grid_bar();   // also orders s_red reads vs next step's writes
    }

    // ---- epilogue: rinv[T] -> hout[T], outs[T-1] ----
    if (w < 8) {
        float p = __ldcg(&g_part[(b0 + w)*NEG + lane]);
        p += __shfl_xor_sync(0xffffffffu, p, 16);
        p += __shfl_xor_sync(0xffffffffu, p, 8);
        p += __shfl_xor_sync(0xffffffffu, p, 4);
        p += __shfl_xor_sync(0xffffffffu, p, 2);
        p += __shfl_xor_sync(0xffffffffu, p, 1);
        float rv = rsqrtf(p * (1.0f/DIM) + 1e-6f);
        float hn = rv * pre_self;
        size_t o = (size_t)(b0 + w)*DIM + e0 + lane;
        hout[(size_t)T_STEPS*BD + o] = hn;
        float sg = 1.0f / (1.0f + __expf(-hn));
        outs[(size_t)(T_STEPS-1)*BD + o] = hn*hn*sg;
    }
}

// ---------------------------------------------------------------------------
extern "C" void kernel_launch(void* const* d_in, const int* in_sizes, int n_in,
                              void* d_out, int out_size) {
    const float* x    = (const float*)d_in[0];
    const float* h0   = (const float*)d_in[1];
    const float* W    = (const float*)d_in[2];
    const float* W_h  = (const float*)d_in[3];
    const float* bias = (const float*)d_in[4];
    const float* la   = (const float*)d_in[5];
    const float* lb   = (const float*)d_in[6];
    float* out = (float*)d_out;

    static int configured = 0;
    if (!configured) {
        cudaFuncSetAttribute(recur, cudaFuncAttributeMaxDynamicSharedMemorySize,
                             SMEM_BYTES);
        configured = 1;
    }

    dim3 ggrid(DIM/128, (T_STEPS*BATCH)/128);   // (8, 128)
    gemm_wx<<<ggrid, 256>>>(x, W, bias, la);
    recur<<<NCTA, NTHR, SMEM_BYTES>>>(h0, W_h, lb, out);
}

// round 9
// speedup vs baseline: 5.1096x; 1.0014x over previous
#include <cuda_runtime.h>
#include <cuda_bf16.h>
#include <math.h>

// Fixed problem shapes
#define T_STEPS 512
#define BATCH   32
#define DIM     1024
#define BD      (BATCH*DIM)          // 32768
#define NCTA    128                  // 32 e-groups x 4 b-groups
#define NTHR    1024                 // 32 warps
#define E_CTA   32                   // e-rows of W_h per CTA (== warp lanes)
#define B_CTA   8                    // batches per CTA group
#define NEG     32                   // e-groups
#define NBG     4                    // b-groups (independent barrier scopes)
#define GRP     32                   // CTAs per barrier group
#define WSTR    1032                 // bf16 elems per smem W row (2064B: conflict-free)

// Device scratch (allocation-free rule)
__device__ float         g_wx [(size_t)T_STEPS*BD];        // alpha*(x@W^T)+alpha*b (fp32)
__device__ __nv_bfloat16 g_hbf[(size_t)(T_STEPS+1)*BD];    // un-normalized pre, bf16
__device__ float         g_part[BATCH*NEG];                // sumsq partials [b][eg]
__device__ unsigned      g_cnt4[NBG*32];                   // 128B-strided counters
__device__ volatile unsigned g_gen4[NBG*32];

// ---------------------------------------------------------------------------
// helpers
// ---------------------------------------------------------------------------
#define FMA2(acc, a, b) \
    asm("fma.rn.f32x2 %0, %1, %2, %0;" : "+l"(acc) : "l"(a), "l"(b))

__device__ __forceinline__ unsigned long long pk2(float x, float y) {
    unsigned long long r;
    asm("mov.b64 %0, {%1,%2};" : "=l"(r)
        : "r"(__float_as_uint(x)), "r"(__float_as_uint(y)));
    return r;
}
__device__ __forceinline__ float2 upk2(unsigned long long v) {
    unsigned lo, hi;
    asm("mov.b64 {%0,%1}, %2;" : "=r"(lo), "=r"(hi) : "l"(v));
    return make_float2(__uint_as_float(lo), __uint_as_float(hi));
}
__device__ __forceinline__ __nv_bfloat162 u2b(unsigned u) {
    return *reinterpret_cast<__nv_bfloat162*>(&u);
}
__device__ __forceinline__ void dot8(__nv_bfloat162& a, uint4 h, uint4 wv) {
    a = __hfma2(u2b(h.x), u2b(wv.x), a);
    a = __hfma2(u2b(h.y), u2b(wv.y), a);
    a = __hfma2(u2b(h.z), u2b(wv.z), a);
    a = __hfma2(u2b(h.w), u2b(wv.w), a);
}

// ---------------------------------------------------------------------------
// Group barrier: only the 32 CTAs sharing a b-group synchronize.
// ---------------------------------------------------------------------------
__device__ __forceinline__ void group_bar(int bg) {
    __threadfence();
    __syncthreads();
    if (threadIdx.x == 0) {
        volatile unsigned* genp = &g_gen4[bg*32];
        unsigned gen = *genp;
        if (atomicAdd(&g_cnt4[bg*32], 1u) == (unsigned)(GRP - 1)) {
            g_cnt4[bg*32] = 0u;
            __threadfence();
            *genp = gen + 1u;
        } else {
            while (*genp == gen) { }
        }
    }
    __syncthreads();
    __threadfence();
}

// ---------------------------------------------------------------------------
// Kernel 1: g_wx[t,b,e] = alpha*(x[t,b,:].W[e,:] + bias[e])   (fp32, FFMA2)
// ---------------------------------------------------------------------------
__global__ void __launch_bounds__(256)
gemm_wx(const float* __restrict__ X, const float* __restrict__ W,
        const float* __restrict__ bias, const float* __restrict__ log_alpha)
{
    __shared__ float As[2][8][136];
    __shared__ float Bs[2][8][136];

    const int tid = threadIdx.x;
    const int tx  = tid & 15;
    const int ty  = tid >> 4;
    const int m0  = blockIdx.y * 128;
    const int e0  = blockIdx.x * 128;
    const int lr  = tid >> 1;
    const int lc  = (tid & 1) * 4;

    unsigned long long ac[8][4];
    #pragma unroll
    for (int i = 0; i < 8; i++)
        #pragma unroll
        for (int j = 0; j < 4; j++) ac[i][j] = 0ull;

    {
        float4 av = *(const float4*)&X[(size_t)(m0 + lr)*DIM + lc];
        float4 bv = *(const float4*)&W[(size_t)(e0 + lr)*DIM + lc];
        As[0][lc+0][lr] = av.x; As[0][lc+1][lr] = av.y;
        As[0][lc+2][lr] = av.z; As[0][lc+3][lr] = av.w;
        Bs[0][lc+0][lr] = bv.x; Bs[0][lc+1][lr] = bv.y;
        Bs[0][lc+2][lr] = bv.z; Bs[0][lc+3][lr] = bv.w;
    }
    __syncthreads();

    for (int k0 = 0; k0 < DIM; k0 += 8) {
        const int buf  = (k0 >> 3) & 1;
        const int nbuf = buf ^ 1;
        float4 av, bv;
        const bool more = (k0 + 8) < DIM;
        if (more) {
            av = *(const float4*)&X[(size_t)(m0 + lr)*DIM + k0 + 8 + lc];
            bv = *(const float4*)&W[(size_t)(e0 + lr)*DIM + k0 + 8 + lc];
        }
        #pragma unroll
        for (int kk = 0; kk < 8; kk++) {
            float4 a0 = *(const float4*)&As[buf][kk][tx*4];
            float4 a1 = *(const float4*)&As[buf][kk][tx*4 + 64];
            ulonglong2 b0 = *(const ulonglong2*)&Bs[buf][kk][ty*4];
            ulonglong2 b1 = *(const ulonglong2*)&Bs[buf][kk][ty*4 + 64];
            float am[8] = {a0.x,a0.y,a0.z,a0.w, a1.x,a1.y,a1.z,a1.w};
            #pragma unroll
            for (int i = 0; i < 8; i++) {
                unsigned long long ad = pk2(am[i], am[i]);
                FMA2(ac[i][0], ad, b0.x);
                FMA2(ac[i][1], ad, b0.y);
                FMA2(ac[i][2], ad, b1.x);
                FMA2(ac[i][3], ad, b1.y);
            }
        }
        if (more) {
            As[nbuf][lc+0][lr] = av.x; As[nbuf][lc+1][lr] = av.y;
            As[nbuf][lc+2][lr] = av.z; As[nbuf][lc+3][lr] = av.w;
            Bs[nbuf][lc+0][lr] = bv.x; Bs[nbuf][lc+1][lr] = bv.y;
            Bs[nbuf][lc+2][lr] = bv.z; Bs[nbuf][lc+3][lr] = bv.w;
        }
        __syncthreads();
    }

    const float alpha = expf(log_alpha[0]);
    float4 bb0 = *(const float4*)&bias[e0 + ty*4];
    float4 bb1 = *(const float4*)&bias[e0 + ty*4 + 64];
    #pragma unroll
    for (int i = 0; i < 8; i++) {
        int m = m0 + ((i < 4) ? (tx*4 + i) : (64 + tx*4 + i - 4));
        float2 p0 = upk2(ac[i][0]);
        float2 p1 = upk2(ac[i][1]);
        float2 p2 = upk2(ac[i][2]);
        float2 p3 = upk2(ac[i][3]);
        float4 o0, o1;
        o0.x = alpha*(p0.x + bb0.x); o0.y = alpha*(p0.y + bb0.y);
        o0.z = alpha*(p1.x + bb0.z); o0.w = alpha*(p1.y + bb0.w);
        o1.x = alpha*(p2.x + bb1.x); o1.y = alpha*(p2.y + bb1.y);
        o1.z = alpha*(p3.x + bb1.z); o1.w = alpha*(p3.y + bb1.w);
        *(float4*)&g_wx[(size_t)m*DIM + e0 + ty*4]      = o0;
        *(float4*)&g_wx[(size_t)m*DIM + e0 + ty*4 + 64] = o1;
    }
}

// ---------------------------------------------------------------------------
// Kernel 2: persistent recurrence. 1024 threads (32 warps), K-split 16,
// per-b-group barrier (32 CTAs). CTA (eg = bid&31, bg = bid>>5):
// e in [eg*32,+32), b in [bg*8,+8).
// Compute role (all 32 warps): bg2 = w&1 (4 b-rows), ks = w>>1 (64-dim slice);
//   lane = e. Per 8-dim chunk: 4 uniform LDG.128 (bf16 h) + 1 LDS.128 + 16 HFMA2.
// Owner role (warps 0-7): b = b0+w, lane = e.
// ---------------------------------------------------------------------------
#define SW_BYTES  (E_CTA*WSTR*2)                    // 66048
#define SRED_OFF  SW_BYTES
#define SMEM_BYTES (SW_BYTES + 16*B_CTA*E_CTA*4)    // +16KB partials = 82432

__global__ void __launch_bounds__(NTHR, 1)
recur(const float* __restrict__ h0, const float* __restrict__ W_h,
      const float* __restrict__ log_beta, float* __restrict__ out)
{
    extern __shared__ char smraw[];
    __nv_bfloat16* s_w   = (__nv_bfloat16*)smraw;
    float*         s_red = (float*)(smraw + SRED_OFF);   // [ks 16][b_l 8][e 32]

    float* outs = out;
    float* hout = out + (size_t)T_STEPS*BD;

    const int tid  = threadIdx.x;
    const int w    = tid >> 5;
    const int lane = tid & 31;
    const int eg   = blockIdx.x & 31;
    const int bg   = blockIdx.x >> 5;
    const int e0   = eg * E_CTA;
    const int b0   = bg * B_CTA;
    const int bg2  = w & 1;          // which 4 of the 8 b's
    const int ks   = w >> 1;         // K slice (64 dims)

    const float beta = 0.1f / (1.0f + expf(-log_beta[0]));

    // Pin W_h rows (bf16) in smem
    for (int i = tid; i < E_CTA*(DIM/4); i += NTHR) {
        int r = i >> 8, q = i & 255;
        float4 v = *(const float4*)&W_h[(size_t)(e0 + r)*DIM + q*4];
        __nv_bfloat162 p0 = __floats2bfloat162_rn(v.x, v.y);
        __nv_bfloat162 p1 = __floats2bfloat162_rn(v.z, v.w);
        *(__nv_bfloat162*)&s_w[r*WSTR + q*4]     = p0;
        *(__nv_bfloat162*)&s_w[r*WSTR + q*4 + 2] = p1;
    }
    // h0 rows of THIS b-group -> g_hbf[0] (bf16) + hout[0] (fp32).
    // Group rows = 8*256 = 2048 float4, sliced across the 32 group CTAs by eg.
    if (tid < 64) {
        int idx = eg*64 + tid;                     // 0..2047
        const float4* src = (const float4*)h0 + (size_t)b0*(DIM/4);
        float4 v = src[idx];
        size_t o4 = (size_t)b0*(DIM/4) + idx;
        ((float4*)hout)[o4] = v;
        __nv_bfloat162 p0 = __floats2bfloat162_rn(v.x, v.y);
        __nv_bfloat162 p1 = __floats2bfloat162_rn(v.z, v.w);
        *(__nv_bfloat162*)&g_hbf[o4*4]     = p0;
        *(__nv_bfloat162*)&g_hbf[o4*4 + 2] = p1;
    }
    // Synthetic partials so rinv[0] == 1
    if (tid < B_CTA)
        g_part[(b0 + tid)*NEG + eg] = (float)E_CTA * (1.0f - 1e-6f);

    float pre_self = 0.f;
    if (w < 8) pre_self = h0[(size_t)(b0 + w)*DIM + e0 + lane];

    group_bar(bg);

    const uint4* wrow = (const uint4*)((const char*)s_w + lane*(WSTR*2) + ks*128);

    for (int t = 0; t < T_STEPS; t++) {
        // ---- owner prefetch: wx + rinv[t] (off the critical path) ----
        float wxv = 0.f, rv = 0.f;
        if (w < 8) {
            wxv = __ldg(&g_wx[(size_t)t*BD + (size_t)(b0 + w)*DIM + e0 + lane]);
            float p = __ldcg(&g_part[(b0 + w)*NEG + lane]);
            p += __shfl_xor_sync(0xffffffffu, p, 16);
            p += __shfl_xor_sync(0xffffffffu, p, 8);
            p += __shfl_xor_sync(0xffffffffu, p, 4);
            p += __shfl_xor_sync(0xffffffffu, p, 2);
            p += __shfl_xor_sync(0xffffffffu, p, 1);
            rv = rsqrtf(p * (1.0f/DIM) + 1e-6f);
        }

        // ---- compute: 4b x 32e x 64k partial dots (bf16, HFMA2) ----
        const __nv_bfloat16* hp =
            g_hbf + (size_t)t*BD + (size_t)(b0 + bg2*4)*DIM + ks*64;
        __nv_bfloat162 a0 = u2b(0u), a1 = u2b(0u), a2 = u2b(0u), a3 = u2b(0u);
        #pragma unroll
        for (int c = 0; c < 8; c++) {
            uint4 wv  = wrow[c];
            uint4 h0v = *(const uint4*)(hp + 0*DIM + c*8);
            uint4 h1v = *(const uint4*)(hp + 1*DIM + c*8);
            uint4 h2v = *(const uint4*)(hp + 2*DIM + c*8);
            uint4 h3v = *(const uint4*)(hp + 3*DIM + c*8);
            dot8(a0, h0v, wv);
            dot8(a1, h1v, wv);
            dot8(a2, h2v, wv);
            dot8(a3, h3v, wv);
        }
        {
            float2 f0 = __bfloat1622float2(a0);
            float2 f1 = __bfloat1622float2(a1);
            float2 f2 = __bfloat1622float2(a2);
            float2 f3 = __bfloat1622float2(a3);
            int base = ks*256 + bg2*128 + lane;
            s_red[base]      = f0.x + f0.y;
            s_red[base + 32] = f1.x + f1.y;
            s_red[base + 64] = f2.x + f2.y;
            s_red[base + 96] = f3.x + f3.y;
        }
        __syncthreads();

        // ---- owner update ----
        if (w < 8) {
            float dot = 0.f;
            #pragma unroll
            for (int k = 0; k < 16; k++)
                dot += s_red[k*256 + w*32 + lane];

            float hn = rv * pre_self;
            size_t o = (size_t)t*BD + (size_t)(b0 + w)*DIM + e0 + lane;
            hout[o] = hn;
            if (t > 0) {
                float sg = 1.0f / (1.0f + __expf(-hn));
                outs[o - BD] = hn*hn*sg;
            }
            float pre_new = hn + wxv + beta * rv * dot;
            g_hbf[o + BD] = __float2bfloat16(pre_new);

            float ss = pre_new * pre_new;
            ss += __shfl_xor_sync(0xffffffffu, ss, 16);
            ss += __shfl_xor_sync(0xffffffffu, ss, 8);
            ss += __shfl_xor_sync(0xffffffffu, ss, 4);
            ss += __shfl_xor_sync(0xffffffffu, ss, 2);
            ss += __shfl_xor_sync(0xffffffffu, ss, 1);
            if (lane == 0) g_part[(b0 + w)*NEG + eg] = ss;
            pre_self = pre_new;
        }

        group_bar(bg);   // only the 32 CTAs of this b-group
    }

    // ---- epilogue: rinv[T] -> hout[T], outs[T-1] ----
    if (w < 8) {
        float p = __ldcg(&g_part[(b0 + w)*NEG + lane]);
        p += __shfl_xor_sync(0xffffffffu, p, 16);
        p += __shfl_xor_sync(0xffffffffu, p, 8);
        p += __shfl_xor_sync(0xffffffffu, p, 4);
        p += __shfl_xor_sync(0xffffffffu, p, 2);
        p += __shfl_xor_sync(0xffffffffu, p, 1);
        float rv = rsqrtf(p * (1.0f/DIM) + 1e-6f);
        float hn = rv * pre_self;
        size_t o = (size_t)(b0 + w)*DIM + e0 + lane;
        hout[(size_t)T_STEPS*BD + o] = hn;
        float sg = 1.0f / (1.0f + __expf(-hn));
        outs[(size_t)(T_STEPS-1)*BD + o] = hn*hn*sg;
    }
}

// ---------------------------------------------------------------------------
extern "C" void kernel_launch(void* const* d_in, const int* in_sizes, int n_in,
                              void* d_out, int out_size) {
    const float* x    = (const float*)d_in[0];
    const float* h0   = (const float*)d_in[1];
    const float* W    = (const float*)d_in[2];
    const float* W_h  = (const float*)d_in[3];
    const float* bias = (const float*)d_in[4];
    const float* la   = (const float*)d_in[5];
    const float* lb   = (const float*)d_in[6];
    float* out = (float*)d_out;

    static int configured = 0;
    if (!configured) {
        cudaFuncSetAttribute(recur, cudaFuncAttributeMaxDynamicSharedMemorySize,
                             SMEM_BYTES);
        configured = 1;
    }

    dim3 ggrid(DIM/128, (T_STEPS*BATCH)/128);   // (8, 128)
    gemm_wx<<<ggrid, 256>>>(x, W, bias, la);
    recur<<<NCTA, NTHR, SMEM_BYTES>>>(h0, W_h, lb, out);
}

// round 10
// speedup vs baseline: 6.1787x; 1.2092x over previous
#include <cuda_runtime.h>
#include <cuda_bf16.h>
#include <math.h>

// Fixed problem shapes
#define T_STEPS 512
#define BATCH   32
#define DIM     1024
#define BD      (BATCH*DIM)          // 32768
#define NCTA    128                  // 32 e-groups x 4 b-groups
#define NTHR    1024                 // 32 warps
#define E_CTA   32
#define B_CTA   8
#define NEG     32
#define NBG     4
#define GRP     32                   // CTAs per barrier group
#define WSTR    1032                 // bf16 elems per smem W row (2064B: conflict-free)

// Device scratch (allocation-free rule)
__device__ float         g_wx [(size_t)T_STEPS*BD];
__device__ __nv_bfloat16 g_hbf[(size_t)(T_STEPS+1)*BD];
__device__ float         g_part[BATCH*NEG];
__device__ unsigned      g_cnt4[NBG*32];                   // 128B-strided
__device__ unsigned      g_gen4[NBG*32];

// ---------------------------------------------------------------------------
// helpers
// ---------------------------------------------------------------------------
#define FMA2(acc, a, b) \
    asm("fma.rn.f32x2 %0, %1, %2, %0;" : "+l"(acc) : "l"(a), "l"(b))

__device__ __forceinline__ unsigned long long pk2(float x, float y) {
    unsigned long long r;
    asm("mov.b64 %0, {%1,%2};" : "=l"(r)
        : "r"(__float_as_uint(x)), "r"(__float_as_uint(y)));
    return r;
}
__device__ __forceinline__ float2 upk2(unsigned long long v) {
    unsigned lo, hi;
    asm("mov.b64 {%0,%1}, %2;" : "=r"(lo), "=r"(hi) : "l"(v));
    return make_float2(__uint_as_float(lo), __uint_as_float(hi));
}
__device__ __forceinline__ __nv_bfloat162 u2b(unsigned u) {
    return *reinterpret_cast<__nv_bfloat162*>(&u);
}
__device__ __forceinline__ void dot8(__nv_bfloat162& a, uint4 h, uint4 wv) {
    a = __hfma2(u2b(h.x), u2b(wv.x), a);
    a = __hfma2(u2b(h.y), u2b(wv.y), a);
    a = __hfma2(u2b(h.z), u2b(wv.z), a);
    a = __hfma2(u2b(h.w), u2b(wv.w), a);
}
__device__ __forceinline__ void cpasync16(void* dst, const void* src) {
    unsigned ds = (unsigned)__cvta_generic_to_shared(dst);
    asm volatile("cp.async.ca.shared.global [%0], [%1], 16;" :: "r"(ds), "l"(src));
}
#define CP_COMMIT() asm volatile("cp.async.commit_group;")
#define CP_WAIT0()  asm volatile("cp.async.wait_group 0;" ::: "memory")

// ---------------------------------------------------------------------------
// Group barrier, split so stores can overlap the spin window:
//   bar_arrive_spin(): sync; thread0 release-arrives and spins.
//   (caller places overlap work here, executed by threads != 0)
//   bar_done(): sync fans the acquire out to the CTA.
// ---------------------------------------------------------------------------
__device__ __forceinline__ void bar_arrive_spin(int bg) {
    __syncthreads();                           // all CTA writes issued
    if (threadIdx.x == 0) {
        unsigned* cnt = &g_cnt4[bg*32];
        unsigned* gen = &g_gen4[bg*32];
        unsigned g;
        asm volatile("ld.relaxed.gpu.global.u32 %0, [%1];" : "=r"(g) : "l"(gen));
        asm volatile("fence.release.gpu;");    // order data writes before RMW
        unsigned old;
        asm volatile("atom.relaxed.gpu.global.add.u32 %0, [%1], 1;"
                     : "=r"(old) : "l"(cnt));
        if (old == (unsigned)(GRP - 1)) {
            asm volatile("st.relaxed.gpu.global.u32 [%0], %1;" :: "l"(cnt), "r"(0u));
            asm volatile("st.release.gpu.global.u32 [%0], %1;" :: "l"(gen), "r"(g + 1u));
        } else {
            unsigned cur;
            do {
                asm volatile("ld.acquire.gpu.global.u32 %0, [%1];" : "=r"(cur) : "l"(gen));
            } while (cur == g);
        }
    }
}
__device__ __forceinline__ void bar_done() { __syncthreads(); }

// ---------------------------------------------------------------------------
// Kernel 1: g_wx[t,b,e] = alpha*(x[t,b,:].W[e,:] + bias[e])   (fp32, FFMA2)
// ---------------------------------------------------------------------------
__global__ void __launch_bounds__(256)
gemm_wx(const float* __restrict__ X, const float* __restrict__ W,
        const float* __restrict__ bias, const float* __restrict__ log_alpha)
{
    __shared__ float As[2][8][136];
    __shared__ float Bs[2][8][136];

    const int tid = threadIdx.x;
    const int tx  = tid & 15;
    const int ty  = tid >> 4;
    const int m0  = blockIdx.y * 128;
    const int e0  = blockIdx.x * 128;
    const int lr  = tid >> 1;
    const int lc  = (tid & 1) * 4;

    unsigned long long ac[8][4];
    #pragma unroll
    for (int i = 0; i < 8; i++)
        #pragma unroll
        for (int j = 0; j < 4; j++) ac[i][j] = 0ull;

    {
        float4 av = *(const float4*)&X[(size_t)(m0 + lr)*DIM + lc];
        float4 bv = *(const float4*)&W[(size_t)(e0 + lr)*DIM + lc];
        As[0][lc+0][lr] = av.x; As[0][lc+1][lr] = av.y;
        As[0][lc+2][lr] = av.z; As[0][lc+3][lr] = av.w;
        Bs[0][lc+0][lr] = bv.x; Bs[0][lc+1][lr] = bv.y;
        Bs[0][lc+2][lr] = bv.z; Bs[0][lc+3][lr] = bv.w;
    }
    __syncthreads();

    for (int k0 = 0; k0 < DIM; k0 += 8) {
        const int buf  = (k0 >> 3) & 1;
        const int nbuf = buf ^ 1;
        float4 av, bv;
        const bool more = (k0 + 8) < DIM;
        if (more) {
            av = *(const float4*)&X[(size_t)(m0 + lr)*DIM + k0 + 8 + lc];
            bv = *(const float4*)&W[(size_t)(e0 + lr)*DIM + k0 + 8 + lc];
        }
        #pragma unroll
        for (int kk = 0; kk < 8; kk++) {
            float4 a0 = *(const float4*)&As[buf][kk][tx*4];
            float4 a1 = *(const float4*)&As[buf][kk][tx*4 + 64];
            ulonglong2 b0 = *(const ulonglong2*)&Bs[buf][kk][ty*4];
            ulonglong2 b1 = *(const ulonglong2*)&Bs[buf][kk][ty*4 + 64];
            float am[8] = {a0.x,a0.y,a0.z,a0.w, a1.x,a1.y,a1.z,a1.w};
            #pragma unroll
            for (int i = 0; i < 8; i++) {
                unsigned long long ad = pk2(am[i], am[i]);
                FMA2(ac[i][0], ad, b0.x);
                FMA2(ac[i][1], ad, b0.y);
                FMA2(ac[i][2], ad, b1.x);
                FMA2(ac[i][3], ad, b1.y);
            }
        }
        if (more) {
            As[nbuf][lc+0][lr] = av.x; As[nbuf][lc+1][lr] = av.y;
            As[nbuf][lc+2][lr] = av.z; As[nbuf][lc+3][lr] = av.w;
            Bs[nbuf][lc+0][lr] = bv.x; Bs[nbuf][lc+1][lr] = bv.y;
            Bs[nbuf][lc+2][lr] = bv.z; Bs[nbuf][lc+3][lr] = bv.w;
        }
        __syncthreads();
    }

    const float alpha = expf(log_alpha[0]);
    float4 bb0 = *(const float4*)&bias[e0 + ty*4];
    float4 bb1 = *(const float4*)&bias[e0 + ty*4 + 64];
    #pragma unroll
    for (int i = 0; i < 8; i++) {
        int m = m0 + ((i < 4) ? (tx*4 + i) : (64 + tx*4 + i - 4));
        float2 p0 = upk2(ac[i][0]);
        float2 p1 = upk2(ac[i][1]);
        float2 p2 = upk2(ac[i][2]);
        float2 p3 = upk2(ac[i][3]);
        float4 o0, o1;
        o0.x = alpha*(p0.x + bb0.x); o0.y = alpha*(p0.y + bb0.y);
        o0.z = alpha*(p1.x + bb0.z); o0.w = alpha*(p1.y + bb0.w);
        o1.x = alpha*(p2.x + bb1.x); o1.y = alpha*(p2.y + bb1.y);
        o1.z = alpha*(p3.x + bb1.z); o1.w = alpha*(p3.y + bb1.w);
        *(float4*)&g_wx[(size_t)m*DIM + e0 + ty*4]      = o0;
        *(float4*)&g_wx[(size_t)m*DIM + e0 + ty*4 + 64] = o1;
    }
}

// ---------------------------------------------------------------------------
// Kernel 2: persistent recurrence. 32 warps, smem-staged h (cp.async),
// release/acquire group barrier, stores overlapped with spin.
// CTA (eg = bid&31, bg = bid>>5): e in [eg*32,+32), b in [bg*8,+8).
// ---------------------------------------------------------------------------
#define SW_BYTES   (E_CTA*WSTR*2)                 // 66048
#define SRED_OFF   SW_BYTES                       // 16KB: [ks 16][b_l 8][e 32] fp32
#define SH_OFF     (SRED_OFF + 16*B_CTA*E_CTA*4)  // 16KB: [b 8][dim 1024] bf16
#define SMEM_BYTES (SH_OFF + B_CTA*DIM*2)         // 98432

__global__ void __launch_bounds__(NTHR, 1)
recur(const float* __restrict__ h0, const float* __restrict__ W_h,
      const float* __restrict__ log_beta, float* __restrict__ out)
{
    extern __shared__ char smraw[];
    __nv_bfloat16* s_w   = (__nv_bfloat16*)smraw;
    float*         s_red = (float*)(smraw + SRED_OFF);
    __nv_bfloat16* s_h   = (__nv_bfloat16*)(smraw + SH_OFF);

    float* outs = out;
    float* hout = out + (size_t)T_STEPS*BD;

    const int tid  = threadIdx.x;
    const int w    = tid >> 5;
    const int lane = tid & 31;
    const int eg   = blockIdx.x & 31;
    const int bg   = blockIdx.x >> 5;
    const int e0   = eg * E_CTA;
    const int b0   = bg * B_CTA;
    const int bg2  = w & 1;          // which 4 of the 8 b's
    const int ks   = w >> 1;         // K slice (64 dims)

    const float beta = 0.1f / (1.0f + expf(-log_beta[0]));

    // Pin W_h rows (bf16) in smem
    for (int i = tid; i < E_CTA*(DIM/4); i += NTHR) {
        int r = i >> 8, q = i & 255;
        float4 v = *(const float4*)&W_h[(size_t)(e0 + r)*DIM + q*4];
        __nv_bfloat162 p0 = __floats2bfloat162_rn(v.x, v.y);
        __nv_bfloat162 p1 = __floats2bfloat162_rn(v.z, v.w);
        *(__nv_bfloat162*)&s_w[r*WSTR + q*4]     = p0;
        *(__nv_bfloat162*)&s_w[r*WSTR + q*4 + 2] = p1;
    }
    // h0 rows of THIS b-group -> g_hbf[0] + hout[0], sliced by eg
    if (tid < 64) {
        int idx = eg*64 + tid;                     // 0..2047
        const float4* src = (const float4*)h0 + (size_t)b0*(DIM/4);
        float4 v = src[idx];
        size_t o4 = (size_t)b0*(DIM/4) + idx;
        ((float4*)hout)[o4] = v;
        __nv_bfloat162 p0 = __floats2bfloat162_rn(v.x, v.y);
        __nv_bfloat162 p1 = __floats2bfloat162_rn(v.z, v.w);
        *(__nv_bfloat162*)&g_hbf[o4*4]     = p0;
        *(__nv_bfloat162*)&g_hbf[o4*4 + 2] = p1;
    }
    if (tid < B_CTA)
        g_part[(b0 + tid)*NEG + eg] = (float)E_CTA * (1.0f - 1e-6f);

    float pre_self = 0.f;
    if (w < 8) pre_self = h0[(size_t)(b0 + w)*DIM + e0 + lane];

    // wx prefetch for t=0 (gemm output: valid before the barrier)
    float wxv_next = 0.f;
    if (w < 8) wxv_next = __ldg(&g_wx[(size_t)(b0 + w)*DIM + e0 + lane]);

    bar_arrive_spin(bg);
    bar_done();

    const uint4* wrow = (const uint4*)((const char*)s_w + lane*(WSTR*2) + ks*128);
    const __nv_bfloat16* hrow = s_h + (size_t)(bg2*4)*DIM + ks*64;

    for (int t = 0; t < T_STEPS; t++) {
        const float wxv = wxv_next;

        // ---- stage h[t] tile (16KB) into smem: coalesced cp.async ----
        cpasync16(s_h + tid*8,
                  g_hbf + (size_t)t*BD + (size_t)b0*DIM + tid*8);
        CP_COMMIT();

        // ---- owners: rinv[t] (L2 read overlaps the cp.async stream) ----
        float rv = 0.f;
        if (w < 8) {
            float p = __ldcg(&g_part[(b0 + w)*NEG + lane]);
            p += __shfl_xor_sync(0xffffffffu, p, 16);
            p += __shfl_xor_sync(0xffffffffu, p, 8);
            p += __shfl_xor_sync(0xffffffffu, p, 4);
            p += __shfl_xor_sync(0xffffffffu, p, 2);
            p += __shfl_xor_sync(0xffffffffu, p, 1);
            rv = rsqrtf(p * (1.0f/DIM) + 1e-6f);
        }
        CP_WAIT0();
        __syncthreads();

        // ---- compute: 4b x 32e x 64k partial dots, both operands in smem ----
        __nv_bfloat162 a0 = u2b(0u), a1 = u2b(0u), a2 = u2b(0u), a3 = u2b(0u);
        #pragma unroll
        for (int c = 0; c < 8; c++) {
            uint4 wv  = wrow[c];
            uint4 h0v = *(const uint4*)(hrow + 0*DIM + c*8);   // LDS bcast
            uint4 h1v = *(const uint4*)(hrow + 1*DIM + c*8);
            uint4 h2v = *(const uint4*)(hrow + 2*DIM + c*8);
            uint4 h3v = *(const uint4*)(hrow + 3*DIM + c*8);
            dot8(a0, h0v, wv);
            dot8(a1, h1v, wv);
            dot8(a2, h2v, wv);
            dot8(a3, h3v, wv);
        }
        {
            float2 f0 = __bfloat1622float2(a0);
            float2 f1 = __bfloat1622float2(a1);
            float2 f2 = __bfloat1622float2(a2);
            float2 f3 = __bfloat1622float2(a3);
            int base = ks*256 + bg2*128 + lane;
            s_red[base]      = f0.x + f0.y;
            s_red[base + 32] = f1.x + f1.y;
            s_red[base + 64] = f2.x + f2.y;
            s_red[base + 96] = f3.x + f3.y;
        }
        // prefetch next step's wx while partials land
        if (w < 8 && t + 1 < T_STEPS)
            wxv_next = __ldg(&g_wx[(size_t)(t+1)*BD + (size_t)(b0 + w)*DIM + e0 + lane]);
        __syncthreads();

        // ---- owner update: ONLY the cross-CTA-visible writes before barrier
        float hn = 0.f;
        if (w < 8) {
            float dot = 0.f;
            #pragma unroll
            for (int k = 0; k < 16; k++)
                dot += s_red[k*256 + w*32 + lane];

            hn = rv * pre_self;
            float pre_new = hn + wxv + beta * rv * dot;
            size_t o = (size_t)t*BD + (size_t)(b0 + w)*DIM + e0 + lane;
            g_hbf[o + BD] = __float2bfloat16(pre_new);

            float ss = pre_new * pre_new;
            ss += __shfl_xor_sync(0xffffffffu, ss, 16);
            ss += __shfl_xor_sync(0xffffffffu, ss, 8);
            ss += __shfl_xor_sync(0xffffffffu, ss, 4);
            ss += __shfl_xor_sync(0xffffffffu, ss, 2);
            ss += __shfl_xor_sync(0xffffffffu, ss, 1);
            if (lane == 0) g_part[(b0 + w)*NEG + eg] = ss;
            pre_self = pre_new;
        }

        bar_arrive_spin(bg);
        // ---- overlap window: local-only stores while thread0 spins ----
        if (w < 8) {
            size_t o = (size_t)t*BD + (size_t)(b0 + w)*DIM + e0 + lane;
            hout[o] = hn;
            if (t > 0) {
                float sg = 1.0f / (1.0f + __expf(-hn));
                outs[o - BD] = hn*hn*sg;
            }
        }
        bar_done();
    }

    // ---- epilogue: rinv[T] -> hout[T], outs[T-1] ----
    if (w < 8) {
        float p = __ldcg(&g_part[(b0 + w)*NEG + lane]);
        p += __shfl_xor_sync(0xffffffffu, p, 16);
        p += __shfl_xor_sync(0xffffffffu, p, 8);
        p += __shfl_xor_sync(0xffffffffu, p, 4);
        p += __shfl_xor_sync(0xffffffffu, p, 2);
        p += __shfl_xor_sync(0xffffffffu, p, 1);
        float rv = rsqrtf(p * (1.0f/DIM) + 1e-6f);
        float hn = rv * pre_self;
        size_t o = (size_t)(b0 + w)*DIM + e0 + lane;
        hout[(size_t)T_STEPS*BD + o] = hn;
        float sg = 1.0f / (1.0f + __expf(-hn));
        outs[(size_t)(T_STEPS-1)*BD + o] = hn*hn*sg;
    }
}

// ---------------------------------------------------------------------------
extern "C" void kernel_launch(void* const* d_in, const int* in_sizes, int n_in,
                              void* d_out, int out_size) {
    const float* x    = (const float*)d_in[0];
    const float* h0   = (const float*)d_in[1];
    const float* W    = (const float*)d_in[2];
    const float* W_h  = (const float*)d_in[3];
    const float* bias = (const float*)d_in[4];
    const float* la   = (const float*)d_in[5];
    const float* lb   = (const float*)d_in[6];
    float* out = (float*)d_out;

    static int configured = 0;
    if (!configured) {
        cudaFuncSetAttribute(recur, cudaFuncAttributeMaxDynamicSharedMemorySize,
                             SMEM_BYTES);
        configured = 1;
    }

    dim3 ggrid(DIM/128, (T_STEPS*BATCH)/128);   // (8, 128)
    gemm_wx<<<ggrid, 256>>>(x, W, bias, la);
    recur<<<NCTA, NTHR, SMEM_BYTES>>>(h0, W_h, lb, out);
}

// round 12
// speedup vs baseline: 6.7677x; 1.0953x over previous
#include <cuda_runtime.h>
#include <cuda_bf16.h>
#include <math.h>

// Fixed problem shapes
#define T_STEPS 512
#define BATCH   32
#define DIM     1024
#define BD      (BATCH*DIM)          // 32768
#define NCTA    128                  // 32 e-groups x 4 b-groups
#define NTHR    1024                 // 32 warps
#define E_CTA   32
#define B_CTA   8
#define NEG     32
#define WSTR    1032                 // bf16 elems per smem W row (2064B: conflict-free)

// Device scratch (allocation-free rule)
__device__ float              g_wx [(size_t)T_STEPS*BD];
__device__ __nv_bfloat16      g_hbf[(size_t)(T_STEPS+1)*BD];
// fused sync+data: [parity][b][eg] = { low32: ss float bits, high32: step tag }
__device__ unsigned long long g_tag[2][BATCH][NEG];

// ---------------------------------------------------------------------------
// helpers
// ---------------------------------------------------------------------------
#define FMA2(acc, a, b) \
    asm("fma.rn.f32x2 %0, %1, %2, %0;" : "+l"(acc) : "l"(a), "l"(b))

__device__ __forceinline__ unsigned long long pk2(float x, float y) {
    unsigned long long r;
    asm("mov.b64 %0, {%1,%2};" : "=l"(r)
        : "r"(__float_as_uint(x)), "r"(__float_as_uint(y)));
    return r;
}
__device__ __forceinline__ float2 upk2(unsigned long long v) {
    unsigned lo, hi;
    asm("mov.b64 {%0,%1}, %2;" : "=r"(lo), "=r"(hi) : "l"(v));
    return make_float2(__uint_as_float(lo), __uint_as_float(hi));
}
__device__ __forceinline__ __nv_bfloat162 u2b(unsigned u) {
    return *reinterpret_cast<__nv_bfloat162*>(&u);
}
__device__ __forceinline__ void dot8(__nv_bfloat162& a, uint4 h, uint4 wv) {
    a = __hfma2(u2b(h.x), u2b(wv.x), a);
    a = __hfma2(u2b(h.y), u2b(wv.y), a);
    a = __hfma2(u2b(h.z), u2b(wv.z), a);
    a = __hfma2(u2b(h.w), u2b(wv.w), a);
}
__device__ __forceinline__ void cpasync16(void* dst, const void* src) {
    unsigned ds = (unsigned)__cvta_generic_to_shared(dst);
    asm volatile("cp.async.ca.shared.global [%0], [%1], 16;" :: "r"(ds), "l"(src));
}
#define CP_COMMIT() asm volatile("cp.async.commit_group;")
#define CP_WAIT0()  asm volatile("cp.async.wait_group 0;" ::: "memory")

// release-publish one {ss, tag} slot
__device__ __forceinline__ void tag_pub(unsigned long long* slot, float ss, unsigned tag) {
    unsigned long long v = ((unsigned long long)tag << 32) | (unsigned long long)__float_as_uint(ss);
    asm volatile("st.release.gpu.global.u64 [%0], %1;" :: "l"(slot), "l"(v) : "memory");
}
// acquire-spin until slot tag == want; returns ss
__device__ __forceinline__ float tag_spin(const unsigned long long* slot, unsigned want) {
    unsigned long long v;
    unsigned done;
    do {
        asm volatile("ld.acquire.gpu.global.u64 %0, [%1];" : "=l"(v) : "l"(slot) : "memory");
        done = ((unsigned)(v >> 32) == want);
    } while (!__all_sync(0xffffffffu, done));
    return __uint_as_float((unsigned)v);
}

// ---------------------------------------------------------------------------
// Kernel 1: g_wx[t,b,e] = alpha*(x[t,b,:].W[e,:] + bias[e])   (fp32, FFMA2)
// CTA(0,0) additionally zero-clears g_tag (stream-ordered before recur).
// ---------------------------------------------------------------------------
__global__ void __launch_bounds__(256)
gemm_wx(const float* __restrict__ X, const float* __restrict__ W,
        const float* __restrict__ bias, const float* __restrict__ log_alpha)
{
    __shared__ float As[2][8][136];
    __shared__ float Bs[2][8][136];

    const int tid = threadIdx.x;
    if (blockIdx.x == 0 && blockIdx.y == 0) {
        unsigned long long* tp = &g_tag[0][0][0];
        for (int i = tid; i < 2*BATCH*NEG; i += 256) tp[i] = 0ull;
    }

    const int tx  = tid & 15;
    const int ty  = tid >> 4;
    const int m0  = blockIdx.y * 128;
    const int e0  = blockIdx.x * 128;
    const int lr  = tid >> 1;
    const int lc  = (tid & 1) * 4;

    unsigned long long ac[8][4];
    #pragma unroll
    for (int i = 0; i < 8; i++)
        #pragma unroll
        for (int j = 0; j < 4; j++) ac[i][j] = 0ull;

    {
        float4 av = *(const float4*)&X[(size_t)(m0 + lr)*DIM + lc];
        float4 bv = *(const float4*)&W[(size_t)(e0 + lr)*DIM + lc];
        As[0][lc+0][lr] = av.x; As[0][lc+1][lr] = av.y;
        As[0][lc+2][lr] = av.z; As[0][lc+3][lr] = av.w;
        Bs[0][lc+0][lr] = bv.x; Bs[0][lc+1][lr] = bv.y;
        Bs[0][lc+2][lr] = bv.z; Bs[0][lc+3][lr] = bv.w;
    }
    __syncthreads();

    for (int k0 = 0; k0 < DIM; k0 += 8) {
        const int buf  = (k0 >> 3) & 1;
        const int nbuf = buf ^ 1;
        float4 av, bv;
        const bool more = (k0 + 8) < DIM;
        if (more) {
            av = *(const float4*)&X[(size_t)(m0 + lr)*DIM + k0 + 8 + lc];
            bv = *(const float4*)&W[(size_t)(e0 + lr)*DIM + k0 + 8 + lc];
        }
        #pragma unroll
        for (int kk = 0; kk < 8; kk++) {
            float4 a0 = *(const float4*)&As[buf][kk][tx*4];
            float4 a1 = *(const float4*)&As[buf][kk][tx*4 + 64];
            ulonglong2 b0 = *(const ulonglong2*)&Bs[buf][kk][ty*4];
            ulonglong2 b1 = *(const ulonglong2*)&Bs[buf][kk][ty*4 + 64];
            float am[8] = {a0.x,a0.y,a0.z,a0.w, a1.x,a1.y,a1.z,a1.w};
            #pragma unroll
            for (int i = 0; i < 8; i++) {
                unsigned long long ad = pk2(am[i], am[i]);
                FMA2(ac[i][0], ad, b0.x);
                FMA2(ac[i][1], ad, b0.y);
                FMA2(ac[i][2], ad, b1.x);
                FMA2(ac[i][3], ad, b1.y);
            }
        }
        if (more) {
            As[nbuf][lc+0][lr] = av.x; As[nbuf][lc+1][lr] = av.y;
            As[nbuf][lc+2][lr] = av.z; As[nbuf][lc+3][lr] = av.w;
            Bs[nbuf][lc+0][lr] = bv.x; Bs[nbuf][lc+1][lr] = bv.y;
            Bs[nbuf][lc+2][lr] = bv.z; Bs[nbuf][lc+3][lr] = bv.w;
        }
        __syncthreads();
    }

    const float alpha = expf(log_alpha[0]);
    float4 bb0 = *(const float4*)&bias[e0 + ty*4];
    float4 bb1 = *(const float4*)&bias[e0 + ty*4 + 64];
    #pragma unroll
    for (int i = 0; i < 8; i++) {
        int m = m0 + ((i < 4) ? (tx*4 + i) : (64 + tx*4 + i - 4));
        float2 p0 = upk2(ac[i][0]);
        float2 p1 = upk2(ac[i][1]);
        float2 p2 = upk2(ac[i][2]);
        float2 p3 = upk2(ac[i][3]);
        float4 o0, o1;
        o0.x = alpha*(p0.x + bb0.x); o0.y = alpha*(p0.y + bb0.y);
        o0.z = alpha*(p1.x + bb0.z); o0.w = alpha*(p1.y + bb0.w);
        o1.x = alpha*(p2.x + bb1.x); o1.y = alpha*(p2.y + bb1.y);
        o1.z = alpha*(p3.x + bb1.z); o1.w = alpha*(p3.y + bb1.w);
        *(float4*)&g_wx[(size_t)m*DIM + e0 + ty*4]      = o0;
        *(float4*)&g_wx[(size_t)m*DIM + e0 + ty*4 + 64] = o1;
    }
}

// ---------------------------------------------------------------------------
// Kernel 2: persistent recurrence. Sync fused into the sumsq-partial word:
//   slot[t&1][b][eg] = { ss(pre[t]) , tag = t+1 }, st.release after the
//   producing CTA's g_hbf[t] writes. Owner-warp rinv spin (ld.acquire until
//   tag==t+1) doubles as the inter-CTA barrier: observing all 32 tags orders
//   all of h[t]. No atomics, no gen flag, ABA-safe (2-deep parity buffer +
//   per-launch clear in gemm_wx).
// CTA (eg = bid&31, bg = bid>>5): e in [eg*32,+32), b in [bg*8,+8).
// ---------------------------------------------------------------------------
#define SW_BYTES   (E_CTA*WSTR*2)                 // 66048
#define SRED_OFF   SW_BYTES                       // 16KB: [ks 16][b_l 8][e 32] fp32
#define SH_OFF     (SRED_OFF + 16*B_CTA*E_CTA*4)  // 16KB: [b 8][dim 1024] bf16
#define SMEM_BYTES (SH_OFF + B_CTA*DIM*2)         // 98432

__global__ void __launch_bounds__(NTHR, 1)
recur(const float* __restrict__ h0, const float* __restrict__ W_h,
      const float* __restrict__ log_beta, float* __restrict__ out)
{
    extern __shared__ char smraw[];
    __nv_bfloat16* s_w   = (__nv_bfloat16*)smraw;
    float*         s_red = (float*)(smraw + SRED_OFF);
    __nv_bfloat16* s_h   = (__nv_bfloat16*)(smraw + SH_OFF);

    float* outs = out;
    float* hout = out + (size_t)T_STEPS*BD;

    const int tid  = threadIdx.x;
    const int w    = tid >> 5;
    const int lane = tid & 31;
    const int eg   = blockIdx.x & 31;
    const int bg   = blockIdx.x >> 5;
    const int e0   = eg * E_CTA;
    const int b0   = bg * B_CTA;
    const int bg2  = w & 1;          // which 4 of the 8 b's
    const int ks   = w >> 1;         // K slice (64 dims)

    const float beta = 0.1f / (1.0f + expf(-log_beta[0]));

    // Pin W_h rows (bf16) in smem
    for (int i = tid; i < E_CTA*(DIM/4); i += NTHR) {
        int r = i >> 8, q = i & 255;
        float4 v = *(const float4*)&W_h[(size_t)(e0 + r)*DIM + q*4];
        __nv_bfloat162 p0 = __floats2bfloat162_rn(v.x, v.y);
        __nv_bfloat162 p1 = __floats2bfloat162_rn(v.z, v.w);
        *(__nv_bfloat162*)&s_w[r*WSTR + q*4]     = p0;
        *(__nv_bfloat162*)&s_w[r*WSTR + q*4 + 2] = p1;
    }
    // h0 rows of THIS b-group -> g_hbf[0] + hout[0], sliced by eg
    if (tid < 64) {
        int idx = eg*64 + tid;                     // 0..2047
        const float4* src = (const float4*)h0 + (size_t)b0*(DIM/4);
        float4 v = src[idx];
        size_t o4 = (size_t)b0*(DIM/4) + idx;
        ((float4*)hout)[o4] = v;
        __nv_bfloat162 p0 = __floats2bfloat162_rn(v.x, v.y);
        __nv_bfloat162 p1 = __floats2bfloat162_rn(v.z, v.w);
        *(__nv_bfloat16*)0; // (no-op placeholder removed by compiler)
        *(__nv_bfloat162*)&g_hbf[o4*4]     = p0;
        *(__nv_bfloat162*)&g_hbf[o4*4 + 2] = p1;
    }
    float pre_self = 0.f;
    if (w < 8) pre_self = h0[(size_t)(b0 + w)*DIM + e0 + lane];
    // wx prefetch for t=0 (gemm finished: prior kernel on the stream)
    float wxv_next = 0.f;
    if (w < 8) wxv_next = __ldg(&g_wx[(size_t)(b0 + w)*DIM + e0 + lane]);

    __syncthreads();   // h0 slice + s_w written by whole CTA

    // Synthetic step-0 partials (rinv[0]==1), released after the h0 writes
    if (tid < B_CTA)
        tag_pub(&g_tag[0][b0 + tid][eg], (float)E_CTA * (1.0f - 1e-6f), 1u);

    for (int t = 0; t < T_STEPS; t++) {
        const float wxv = wxv_next;

        // ---- owners: spin on the 32 fused {ss,tag} words == t+1, reduce ----
        float rv = 0.f;
        if (w < 8) {
            float p = tag_spin(&g_tag[t & 1][b0 + w][lane], (unsigned)(t + 1));
            p += __shfl_xor_sync(0xffffffffu, p, 16);
            p += __shfl_xor_sync(0xffffffffu, p, 8);
            p += __shfl_xor_sync(0xffffffffu, p, 4);
            p += __shfl_xor_sync(0xffffffffu, p, 2);
            p += __shfl_xor_sync(0xffffffffu, p, 1);
            rv = rsqrtf(p * (1.0f/DIM) + 1e-6f);
        }
        __syncthreads();   // gate: g_hbf[t] globally visible to all warps

        // ---- stage h[t] tile (16KB) into smem: coalesced cp.async ----
        cpasync16(s_h + tid*8,
                  g_hbf + (size_t)t*BD + (size_t)b0*DIM + tid*8);
        CP_COMMIT();
        CP_WAIT0();
        __syncthreads();

        // ---- compute: 4b x 32e x 64k partial dots, both operands in smem ----
        const uint4* wrow = (const uint4*)((const char*)s_w + lane*(WSTR*2) + ks*128);
        const __nv_bfloat16* hrow = s_h + (size_t)(bg2*4)*DIM + ks*64;
        __nv_bfloat162 a0 = u2b(0u), a1 = u2b(0u), a2 = u2b(0u), a3 = u2b(0u);
        #pragma unroll
        for (int c = 0; c < 8; c++) {
            uint4 wv  = wrow[c];
            uint4 h0v = *(const uint4*)(hrow + 0*DIM + c*8);   // LDS bcast
            uint4 h1v = *(const uint4*)(hrow + 1*DIM + c*8);
            uint4 h2v = *(const uint4*)(hrow + 2*DIM + c*8);
            uint4 h3v = *(const uint4*)(hrow + 3*DIM + c*8);
            dot8(a0, h0v, wv);
            dot8(a1, h1v, wv);
            dot8(a2, h2v, wv);
            dot8(a3, h3v, wv);
        }
        {
            float2 f0 = __bfloat1622float2(a0);
            float2 f1 = __bfloat1622float2(a1);
            float2 f2 = __bfloat1622float2(a2);
            float2 f3 = __bfloat1622float2(a3);
            int base = ks*256 + bg2*128 + lane;
            s_red[base]      = f0.x + f0.y;
            s_red[base + 32] = f1.x + f1.y;
            s_red[base + 64] = f2.x + f2.y;
            s_red[base + 96] = f3.x + f3.y;
        }
        // prefetch next step's wx while partials land
        if (w < 8 && t + 1 < T_STEPS)
            wxv_next = __ldg(&g_wx[(size_t)(t+1)*BD + (size_t)(b0 + w)*DIM + e0 + lane]);
        __syncthreads();

        // ---- owner update: publish h[t+1] + fused {ss, tag} ASAP ----
        if (w < 8) {
            float dot = 0.f;
            #pragma unroll
            for (int k = 0; k < 16; k++)
                dot += s_red[k*256 + w*32 + lane];

            float hn = rv * pre_self;
            float pre_new = hn + wxv + beta * rv * dot;
            size_t o = (size_t)t*BD + (size_t)(b0 + w)*DIM + e0 + lane;
            g_hbf[o + BD] = __float2bfloat16(pre_new);

            float ss = pre_new * pre_new;
            ss += __shfl_xor_sync(0xffffffffu, ss, 16);
            ss += __shfl_xor_sync(0xffffffffu, ss, 8);
            ss += __shfl_xor_sync(0xffffffffu, ss, 4);
            ss += __shfl_xor_sync(0xffffffffu, ss, 2);
            ss += __shfl_xor_sync(0xffffffffu, ss, 1);
            __syncwarp();   // all lanes' g_hbf stores ordered before release
            if (lane == 0)
                tag_pub(&g_tag[(t + 1) & 1][b0 + w][eg], ss, (unsigned)(t + 2));
            pre_self = pre_new;

            // local-only stores: overlap with other CTAs' spins
            hout[o] = hn;
            if (t > 0) {
                float sg = 1.0f / (1.0f + __expf(-hn));
                outs[o - BD] = hn*hn*sg;
            }
        }
    }

    // ---- epilogue: rinv[T] -> hout[T], outs[T-1] ----
    if (w < 8) {
        float p = tag_spin(&g_tag[T_STEPS & 1][b0 + w][lane], (unsigned)(T_STEPS + 1));
        p += __shfl_xor_sync(0xffffffffu, p, 16);
        p += __shfl_xor_sync(0xffffffffu, p, 8);
        p += __shfl_xor_sync(0xffffffffu, p, 4);
        p += __shfl_xor_sync(0xffffffffu, p, 2);
        p += __shfl_xor_sync(0xffffffffu, p, 1);
        float rv = rsqrtf(p * (1.0f/DIM) + 1e-6f);
        float hn = rv * pre_self;
        size_t o = (size_t)(b0 + w)*DIM + e0 + lane;
        hout[(size_t)T_STEPS*BD + o] = hn;
        float sg = 1.0f / (1.0f + __expf(-hn));
        outs[(size_t)(T_STEPS-1)*BD + o] = hn*hn*sg;
    }
}

// ---------------------------------------------------------------------------
extern "C" void kernel_launch(void* const* d_in, const int* in_sizes, int n_in,
                              void* d_out, int out_size) {
    const float* x    = (const float*)d_in[0];
    const float* h0   = (const float*)d_in[1];
    const float* W    = (const float*)d_in[2];
    const float* W_h  = (const float*)d_in[3];
    const float* bias = (const float*)d_in[4];
    const float* la   = (const float*)d_in[5];
    const float* lb   = (const float*)d_in[6];
    float* out = (float*)d_out;

    static int configured = 0;
    if (!configured) {
        cudaFuncSetAttribute(recur, cudaFuncAttributeMaxDynamicSharedMemorySize,
                             SMEM_BYTES);
        configured = 1;
    }

    dim3 ggrid(DIM/128, (T_STEPS*BATCH)/128);   // (8, 128)
    gemm_wx<<<ggrid, 256>>>(x, W, bias, la);
    recur<<<NCTA, NTHR, SMEM_BYTES>>>(h0, W_h, lb, out);
}